// round 6
// baseline (speedup 1.0000x reference)
#include <cuda_runtime.h>
#include <cuda_bf16.h>
#include <math.h>

// Problem constants
#define S 2048
#define D_MODEL 2560
#define NUM_HEADS 32
#define NUM_KV_HEADS 8
#define HEAD_DIM 128
#define QDIM (NUM_HEADS * HEAD_DIM)     // 4096
#define KVDIM (NUM_KV_HEADS * HEAD_DIM) // 1024
#define QKVDIM (QDIM + 2 * KVDIM)       // 6144
#define EPS 1e-6f
#define ROPE_THETA 5000000.0f

// Scratch (no allocs allowed -> __device__ globals)
__device__ float g_X[S * D_MODEL];        // tf32-rounded x
__device__ float g_Wqkv[QKVDIM * D_MODEL];// tf32-rounded [Wq;Wk;Wv]
__device__ float g_Wo[D_MODEL * QDIM];    // tf32-rounded Wo
__device__ float g_QKV[S * QKVDIM];       // raw qkv projections
__device__ float g_Q[S * QDIM];           // normed+roped Q (tf32-rounded)
__device__ float g_O[S * QDIM];           // attention out (tf32-rounded)

// ----------------------------------------------------------------------------
// helpers
// ----------------------------------------------------------------------------
__device__ __forceinline__ float tf32r(float x) {
    unsigned u;
    asm("cvt.rna.tf32.f32 %0, %1;" : "=r"(u) : "f"(x));
    return __uint_as_float(u);
}

__device__ __forceinline__ void mma_tf32(float* d, const unsigned* a, const unsigned* b) {
    asm volatile(
        "mma.sync.aligned.m16n8k8.row.col.f32.tf32.tf32.f32 "
        "{%0,%1,%2,%3}, {%4,%5,%6,%7}, {%8,%9}, {%0,%1,%2,%3};"
        : "+f"(d[0]), "+f"(d[1]), "+f"(d[2]), "+f"(d[3])
        : "r"(a[0]), "r"(a[1]), "r"(a[2]), "r"(a[3]), "r"(b[0]), "r"(b[1]));
}

__device__ __forceinline__ void cp_async16(void* smem_dst, const void* gmem_src) {
    unsigned saddr = (unsigned)__cvta_generic_to_shared(smem_dst);
    asm volatile("cp.async.cg.shared.global [%0], [%1], 16;" :: "r"(saddr), "l"(gmem_src));
}
#define CP_COMMIT() asm volatile("cp.async.commit_group;")
#define CP_WAIT1()  asm volatile("cp.async.wait_group 1;")

// ----------------------------------------------------------------------------
// Pre-round to tf32 (RNA), vectorized
// ----------------------------------------------------------------------------
__global__ void round_tf32_kernel(const float* __restrict__ src, float* __restrict__ dst,
                                  int n4) {
    int i = blockIdx.x * blockDim.x + threadIdx.x;
    if (i < n4) {
        float4 v = ((const float4*)src)[i];
        v.x = tf32r(v.x); v.y = tf32r(v.y); v.z = tf32r(v.z); v.w = tf32r(v.w);
        ((float4*)dst)[i] = v;
    }
}

// ----------------------------------------------------------------------------
// tf32 NT GEMM v2: C[M,N] = A[M,K] @ B[N,K]^T, inputs pre-rounded to tf32.
// Tile 128x128x32, 256 threads (8 warps, 2x4), warp tile 64x32.
// 3-stage cp.async pipeline, 1 syncthreads/iter. ldc parameterized.
// ----------------------------------------------------------------------------
#define BM2 128
#define BN2 128
#define BK2 32
#define ST2 36                 // smem row stride (==4 mod 32: conflict-free)
#define STAGE_FLOATS ((BM2 + BN2) * ST2)
#define GSTAGES 3
#define G2_SMEM (GSTAGES * STAGE_FLOATS * 4)   // 110592 B

__global__ __launch_bounds__(256) void gemm_tf32_v2(const float* __restrict__ A,
                                                    const float* __restrict__ B,
                                                    float* __restrict__ C,
                                                    int M, int N, int K, int ldc) {
    extern __shared__ float sm2[];

    const int tid = threadIdx.x;
    const int warp = tid >> 5;
    const int lane = tid & 31;
    const int wm = warp >> 2;       // 0..1 (64 rows)
    const int wn = warp & 3;        // 0..3 (32 cols)
    const int r = lane >> 2;        // 0..7
    const int cc = lane & 3;        // 0..3
    const int bm0 = blockIdx.y * BM2;
    const int bn0 = blockIdx.x * BN2;

    const int lrow = tid >> 3;      // 0..31
    const int lch = tid & 7;        // 0..7 (16B chunk)

    const int nk = K / BK2;

    // issue stage kt
    auto issue = [&](int kt) {
        float* As = sm2 + (kt % GSTAGES) * STAGE_FLOATS;
        float* Bs = As + BM2 * ST2;
        int k0 = kt * BK2;
#pragma unroll
        for (int i = 0; i < 4; i++) {
            int row = lrow + i * 32;
            cp_async16(&As[row * ST2 + lch * 4],
                       &A[(size_t)(bm0 + row) * K + k0 + lch * 4]);
        }
#pragma unroll
        for (int i = 0; i < 4; i++) {
            int row = lrow + i * 32;
            cp_async16(&Bs[row * ST2 + lch * 4],
                       &B[(size_t)(bn0 + row) * K + k0 + lch * 4]);
        }
        CP_COMMIT();
    };

    issue(0);
    issue(1);

    float acc[4][4][4];
#pragma unroll
    for (int mt = 0; mt < 4; mt++)
#pragma unroll
        for (int nt = 0; nt < 4; nt++)
#pragma unroll
            for (int i = 0; i < 4; i++) acc[mt][nt][i] = 0.0f;

    for (int kt = 0; kt < nk; kt++) {
        CP_WAIT1();              // stage kt resident (<=1 group pending)
        __syncthreads();

        const float* As = sm2 + (kt % GSTAGES) * STAGE_FLOATS;
        const float* Bs = As + BM2 * ST2;

#pragma unroll
        for (int ks = 0; ks < 4; ks++) {
            unsigned af[4][4];
#pragma unroll
            for (int mt = 0; mt < 4; mt++) {
                int m0 = wm * 64 + mt * 16;
                af[mt][0] = __float_as_uint(As[(m0 + r) * ST2 + ks * 8 + cc]);
                af[mt][1] = __float_as_uint(As[(m0 + r + 8) * ST2 + ks * 8 + cc]);
                af[mt][2] = __float_as_uint(As[(m0 + r) * ST2 + ks * 8 + cc + 4]);
                af[mt][3] = __float_as_uint(As[(m0 + r + 8) * ST2 + ks * 8 + cc + 4]);
            }
            unsigned bf[4][2];
#pragma unroll
            for (int nt = 0; nt < 4; nt++) {
                int n0 = wn * 32 + nt * 8 + r;
                bf[nt][0] = __float_as_uint(Bs[n0 * ST2 + ks * 8 + cc]);
                bf[nt][1] = __float_as_uint(Bs[n0 * ST2 + ks * 8 + cc + 4]);
            }
#pragma unroll
            for (int mt = 0; mt < 4; mt++)
#pragma unroll
                for (int nt = 0; nt < 4; nt++)
                    mma_tf32(acc[mt][nt], af[mt], bf[nt]);
        }

        if (kt + GSTAGES - 1 < nk) issue(kt + GSTAGES - 1);
    }

    // epilogue
#pragma unroll
    for (int mt = 0; mt < 4; mt++) {
#pragma unroll
        for (int nt = 0; nt < 4; nt++) {
            int row = bm0 + wm * 64 + mt * 16 + r;
            int col = bn0 + wn * 32 + nt * 8 + 2 * cc;
            float2 v0 = make_float2(acc[mt][nt][0], acc[mt][nt][1]);
            float2 v1 = make_float2(acc[mt][nt][2], acc[mt][nt][3]);
            *(float2*)&C[(size_t)row * ldc + col] = v0;
            *(float2*)&C[(size_t)(row + 8) * ldc + col] = v1;
        }
    }
}

// ----------------------------------------------------------------------------
// RMSNorm + RoPE, reading from fused QKV buffer.
// mode 0 (Q): dst[s*4096 + h*128 + d], tf32-rounded (internal use only).
// mode 1 (K): dst[(h*S+s)*128 + d], full fp32 (this IS the cache_k output).
// ----------------------------------------------------------------------------
__global__ void norm_rope_kernel(const float* __restrict__ src, float* __restrict__ dst,
                                 const float* __restrict__ w, int src_off, int dst_is_cache) {
    int s = blockIdx.x;
    int h = blockIdx.y;
    int d = threadIdx.x;

    __shared__ float sh[HEAD_DIM];
    __shared__ float red[4];

    float x = src[(size_t)s * QKVDIM + src_off + h * HEAD_DIM + d];

    float sq = x * x;
#pragma unroll
    for (int off = 16; off > 0; off >>= 1)
        sq += __shfl_down_sync(0xffffffff, sq, off);
    if ((d & 31) == 0) red[d >> 5] = sq;
    __syncthreads();
    float var = (red[0] + red[1] + red[2] + red[3]) * (1.0f / HEAD_DIM);
    float r = rsqrtf(var + EPS);
    float xn = x * r * w[d];
    sh[d] = xn;
    __syncthreads();

    int f = d & 63;
    float inv_freq = powf(ROPE_THETA, -((float)f) / 64.0f);
    float ang = (float)s * inv_freq;
    float c = cosf(ang), sn = sinf(ang);
    float out;
    if (d < 64) out = xn * c - sh[d + 64] * sn;
    else        out = xn * c + sh[d - 64] * sn;

    if (dst_is_cache) {
        dst[((size_t)h * S + s) * HEAD_DIM + d] = out;           // full precision
    } else {
        dst[(size_t)s * QDIM + h * HEAD_DIM + d] = tf32r(out);   // internal
    }
}

// V: [s, qkv] -> cache [g, s, d] (full fp32, this IS cache_v)
__global__ void v_to_cache_kernel(const float* __restrict__ src, float* __restrict__ dst) {
    int s = blockIdx.x;
    int g = blockIdx.y;
    int d = threadIdx.x;
    dst[((size_t)g * S + s) * HEAD_DIM + d] =
        src[(size_t)s * QKVDIM + QDIM + KVDIM + g * HEAD_DIM + d];
}

// ----------------------------------------------------------------------------
// Flash attention with tf32 mma (unchanged structure from round 5; Q already
// rounded, O written rounded).
// ----------------------------------------------------------------------------
#define FQT 64
#define FKT 64
#define QS_OFF 0
#define KV_OFF 8448
#define PS_OFF 17152
#define MS_OFF 21504
#define LS_OFF 21568
#define CS_OFF 21632
#define FSMEM_FLOATS 21696

__global__ __launch_bounds__(128) void flash_tf32(const float* __restrict__ cacheK,
                                                  const float* __restrict__ cacheV) {
    extern __shared__ float fsm[];
    float* Qs = fsm + QS_OFF;      // stride 132
    float* KVs = fsm + KV_OFF;     // K stride 132 / V^T stride 68
    float* Ps = fsm + PS_OFF;      // stride 68
    float* mS = fsm + MS_OFF;
    float* lS = fsm + LS_OFF;
    float* corrS = fsm + CS_OFF;

    const int qTile = blockIdx.x;
    const int h = blockIdx.y;
    const int g = h >> 2;
    const int tid = threadIdx.x;
    const int warp = tid >> 5;
    const int lane = tid & 31;
    const int wm = warp >> 1;
    const int wn = warp & 1;
    const int r = lane >> 2;
    const int cc = lane & 3;
    const int qBase = qTile * FQT;
    const float scale = 0.08838834764831845f;

    if (tid < 64) { mS[tid] = -INFINITY; lS[tid] = 0.0f; }

    // Q already tf32-rounded
#pragma unroll
    for (int i = 0; i < 16; i++) {
        int idx = tid + i * 128;
        int row = idx >> 5, c4 = idx & 31;
        float4 v = *(const float4*)&g_Q[(size_t)(qBase + row) * QDIM + h * HEAD_DIM + c4 * 4];
        *(float4*)&Qs[row * 132 + c4 * 4] = v;
    }

    float oacc[2][8][4];
#pragma unroll
    for (int mt = 0; mt < 2; mt++)
#pragma unroll
        for (int nt = 0; nt < 8; nt++)
#pragma unroll
            for (int i = 0; i < 4; i++) oacc[mt][nt][i] = 0.0f;

    __syncthreads();

    for (int kt = 0; kt <= qTile; kt++) {
        const int kBase = kt * FKT;

#pragma unroll
        for (int i = 0; i < 16; i++) {
            int idx = tid + i * 128;
            int row = idx >> 5, c4 = idx & 31;
            float4 v = *(const float4*)&cacheK[((size_t)g * S + kBase + row) * HEAD_DIM + c4 * 4];
            v.x = tf32r(v.x); v.y = tf32r(v.y); v.z = tf32r(v.z); v.w = tf32r(v.w);
            *(float4*)&KVs[row * 132 + c4 * 4] = v;
        }
        __syncthreads();

        float sacc[2][4][4];
#pragma unroll
        for (int mt = 0; mt < 2; mt++)
#pragma unroll
            for (int nt = 0; nt < 4; nt++)
#pragma unroll
                for (int i = 0; i < 4; i++) sacc[mt][nt][i] = 0.0f;

#pragma unroll
        for (int ks = 0; ks < 16; ks++) {
            unsigned af[2][4];
#pragma unroll
            for (int mt = 0; mt < 2; mt++) {
                int m0 = wm * 32 + mt * 16;
                af[mt][0] = __float_as_uint(Qs[(m0 + r) * 132 + ks * 8 + cc]);
                af[mt][1] = __float_as_uint(Qs[(m0 + r + 8) * 132 + ks * 8 + cc]);
                af[mt][2] = __float_as_uint(Qs[(m0 + r) * 132 + ks * 8 + cc + 4]);
                af[mt][3] = __float_as_uint(Qs[(m0 + r + 8) * 132 + ks * 8 + cc + 4]);
            }
            unsigned bf[4][2];
#pragma unroll
            for (int nt = 0; nt < 4; nt++) {
                int n0 = wn * 32 + nt * 8 + r;
                bf[nt][0] = __float_as_uint(KVs[n0 * 132 + ks * 8 + cc]);
                bf[nt][1] = __float_as_uint(KVs[n0 * 132 + ks * 8 + cc + 4]);
            }
#pragma unroll
            for (int mt = 0; mt < 2; mt++)
#pragma unroll
                for (int nt = 0; nt < 4; nt++)
                    mma_tf32(sacc[mt][nt], af[mt], bf[nt]);
        }

#pragma unroll
        for (int mt = 0; mt < 2; mt++) {
#pragma unroll
            for (int nt = 0; nt < 4; nt++) {
                int row0 = wm * 32 + mt * 16 + r;
                int col0 = wn * 32 + nt * 8 + 2 * cc;
                int qi0 = qBase + row0, qi1 = qi0 + 8;
                int kj0 = kBase + col0, kj1 = kj0 + 1;
                Ps[row0 * 68 + col0]       = (kj0 <= qi0) ? sacc[mt][nt][0] * scale : -1e30f;
                Ps[row0 * 68 + col0 + 1]   = (kj1 <= qi0) ? sacc[mt][nt][1] * scale : -1e30f;
                Ps[(row0 + 8) * 68 + col0]     = (kj0 <= qi1) ? sacc[mt][nt][2] * scale : -1e30f;
                Ps[(row0 + 8) * 68 + col0 + 1] = (kj1 <= qi1) ? sacc[mt][nt][3] * scale : -1e30f;
            }
        }
        __syncthreads();

        // V^T load (K no longer needed)
#pragma unroll
        for (int i = 0; i < 16; i++) {
            int idx = tid + i * 128;
            int s = idx & 63, c4 = idx >> 6;
            float4 v = *(const float4*)&cacheV[((size_t)g * S + kBase + s) * HEAD_DIM + c4 * 4];
            KVs[(c4 * 4 + 0) * 68 + s] = tf32r(v.x);
            KVs[(c4 * 4 + 1) * 68 + s] = tf32r(v.y);
            KVs[(c4 * 4 + 2) * 68 + s] = tf32r(v.z);
            KVs[(c4 * 4 + 3) * 68 + s] = tf32r(v.w);
        }

        // online softmax
        {
            int row = tid >> 1;
            int half = tid & 1;
            float* prow = &Ps[row * 68 + half * 32];
            float mloc = -INFINITY;
#pragma unroll 8
            for (int j = 0; j < 32; j++) mloc = fmaxf(mloc, prow[j]);
            mloc = fmaxf(mloc, __shfl_xor_sync(0xffffffffu, mloc, 1));
            float mprev = mS[row];
            float mnew = fmaxf(mprev, mloc);
            float lsum = 0.0f;
#pragma unroll 8
            for (int j = 0; j < 32; j++) {
                float p = __expf(prow[j] - mnew);
                lsum += p;
                prow[j] = tf32r(p);
            }
            lsum += __shfl_xor_sync(0xffffffffu, lsum, 1);
            if (half == 0) {
                float corr = __expf(mprev - mnew);
                corrS[row] = corr;
                lS[row] = lS[row] * corr + lsum;
                mS[row] = mnew;
            }
        }
        __syncthreads();

#pragma unroll
        for (int mt = 0; mt < 2; mt++) {
            int row0 = wm * 32 + mt * 16 + r;
            float cr0 = corrS[row0];
            float cr1 = corrS[row0 + 8];
#pragma unroll
            for (int nt = 0; nt < 8; nt++) {
                oacc[mt][nt][0] *= cr0; oacc[mt][nt][1] *= cr0;
                oacc[mt][nt][2] *= cr1; oacc[mt][nt][3] *= cr1;
            }
        }

#pragma unroll
        for (int ks = 0; ks < 8; ks++) {
            unsigned af[2][4];
#pragma unroll
            for (int mt = 0; mt < 2; mt++) {
                int m0 = wm * 32 + mt * 16;
                af[mt][0] = __float_as_uint(Ps[(m0 + r) * 68 + ks * 8 + cc]);
                af[mt][1] = __float_as_uint(Ps[(m0 + r + 8) * 68 + ks * 8 + cc]);
                af[mt][2] = __float_as_uint(Ps[(m0 + r) * 68 + ks * 8 + cc + 4]);
                af[mt][3] = __float_as_uint(Ps[(m0 + r + 8) * 68 + ks * 8 + cc + 4]);
            }
#pragma unroll
            for (int nt = 0; nt < 8; nt++) {
                int n0 = wn * 64 + nt * 8 + r;
                unsigned bf[2];
                bf[0] = __float_as_uint(KVs[n0 * 68 + ks * 8 + cc]);
                bf[1] = __float_as_uint(KVs[n0 * 68 + ks * 8 + cc + 4]);
#pragma unroll
                for (int mt = 0; mt < 2; mt++)
                    mma_tf32(oacc[mt][nt], af[mt], bf);
            }
        }
        __syncthreads();
    }

    // epilogue: normalize, round to tf32 (it feeds the final GEMM), write
#pragma unroll
    for (int mt = 0; mt < 2; mt++) {
        int row0 = wm * 32 + mt * 16 + r;
        float li0 = 1.0f / lS[row0];
        float li1 = 1.0f / lS[row0 + 8];
#pragma unroll
        for (int nt = 0; nt < 8; nt++) {
            int col = wn * 64 + nt * 8 + 2 * cc;
            float2 v0 = make_float2(tf32r(oacc[mt][nt][0] * li0), tf32r(oacc[mt][nt][1] * li0));
            float2 v1 = make_float2(tf32r(oacc[mt][nt][2] * li1), tf32r(oacc[mt][nt][3] * li1));
            *(float2*)&g_O[(size_t)(qBase + row0) * QDIM + h * HEAD_DIM + col] = v0;
            *(float2*)&g_O[(size_t)(qBase + row0 + 8) * QDIM + h * HEAD_DIM + col] = v1;
        }
    }
}

// ----------------------------------------------------------------------------
extern "C" void kernel_launch(void* const* d_in, const int* in_sizes, int n_in,
                              void* d_out, int out_size) {
    const float* x  = (const float*)d_in[0];
    const float* Wq = (const float*)d_in[1];
    const float* Wk = (const float*)d_in[2];
    const float* Wv = (const float*)d_in[3];
    const float* Wo = (const float*)d_in[4];
    const float* qw = (const float*)d_in[5];
    const float* kw = (const float*)d_in[6];

    float* out    = (float*)d_out;
    float* cacheK = out + (size_t)S * D_MODEL;
    float* cacheV = cacheK + (size_t)NUM_KV_HEADS * S * HEAD_DIM;

    float* dX;  cudaGetSymbolAddress((void**)&dX, g_X);
    float* dWqkv; cudaGetSymbolAddress((void**)&dWqkv, g_Wqkv);
    float* dWo; cudaGetSymbolAddress((void**)&dWo, g_Wo);
    float* dQKV; cudaGetSymbolAddress((void**)&dQKV, g_QKV);
    float* dQ; cudaGetSymbolAddress((void**)&dQ, g_Q);
    float* dO; cudaGetSymbolAddress((void**)&dO, g_O);

    // 0) pre-round inputs to tf32 (RNA) once
    {
        int n;
        n = S * D_MODEL / 4;
        round_tf32_kernel<<<(n + 255) / 256, 256>>>(x, dX, n);
        n = QDIM * D_MODEL / 4;
        round_tf32_kernel<<<(n + 255) / 256, 256>>>(Wq, dWqkv, n);
        n = KVDIM * D_MODEL / 4;
        round_tf32_kernel<<<(n + 255) / 256, 256>>>(Wk, dWqkv + (size_t)QDIM * D_MODEL, n);
        round_tf32_kernel<<<(n + 255) / 256, 256>>>(Wv, dWqkv + (size_t)(QDIM + KVDIM) * D_MODEL, n);
        n = D_MODEL * QDIM / 4;
        round_tf32_kernel<<<(n + 255) / 256, 256>>>(Wo, dWo, n);
    }

    cudaFuncSetAttribute(gemm_tf32_v2, cudaFuncAttributeMaxDynamicSharedMemorySize, G2_SMEM);

    // 1) fused QKV projection: [2048, 6144] = X @ [Wq;Wk;Wv]^T
    gemm_tf32_v2<<<dim3(QKVDIM / BN2, S / BM2), 256, G2_SMEM>>>(
        dX, dWqkv, dQKV, S, QKVDIM, D_MODEL, QKVDIM);

    // 2) RMSNorm + RoPE (Q -> g_Q rounded; K -> cache fp32), V -> cache fp32
    norm_rope_kernel<<<dim3(S, NUM_HEADS), HEAD_DIM>>>(dQKV, dQ, qw, 0, 0);
    norm_rope_kernel<<<dim3(S, NUM_KV_HEADS), HEAD_DIM>>>(dQKV, cacheK, kw, QDIM, 1);
    v_to_cache_kernel<<<dim3(S, NUM_KV_HEADS), HEAD_DIM>>>(dQKV, cacheV);

    // 3) Flash attention (tf32 mma)
    {
        size_t smem_bytes = FSMEM_FLOATS * sizeof(float); // 86784
        cudaFuncSetAttribute(flash_tf32, cudaFuncAttributeMaxDynamicSharedMemorySize,
                             (int)smem_bytes);
        flash_tf32<<<dim3(S / FQT, NUM_HEADS), 128, smem_bytes>>>(cacheK, cacheV);
    }

    // 4) Output projection: out = O @ Wo^T
    gemm_tf32_v2<<<dim3(D_MODEL / BN2, S / BM2), 256, G2_SMEM>>>(
        dO, dWo, out, S, D_MODEL, QDIM, D_MODEL);
}

// round 7
// speedup vs baseline: 1.2693x; 1.2693x over previous
#include <cuda_runtime.h>
#include <cuda_bf16.h>
#include <math.h>

// Problem constants
#define S 2048
#define D_MODEL 2560
#define NUM_HEADS 32
#define NUM_KV_HEADS 8
#define HEAD_DIM 128
#define QDIM (NUM_HEADS * HEAD_DIM)     // 4096
#define KVDIM (NUM_KV_HEADS * HEAD_DIM) // 1024
#define QKVDIM (QDIM + 2 * KVDIM)       // 6144
#define EPS 1e-6f
#define ROPE_THETA 5000000.0f

// Scratch (no allocs allowed -> __device__ globals)
__device__ float g_X[S * D_MODEL];         // tf32-rounded x
__device__ float g_Wqkv[QKVDIM * D_MODEL]; // tf32-rounded [Wq;Wk;Wv]
__device__ float g_Wo[D_MODEL * QDIM];     // tf32-rounded Wo
__device__ float g_QKV[S * QKVDIM];        // raw qkv projections
__device__ float g_Q[S * QDIM];            // normed+roped Q (tf32-rounded)
__device__ float g_Kr[NUM_KV_HEADS * S * HEAD_DIM]; // rounded K cache [g,s,d]
__device__ float g_Vr[NUM_KV_HEADS * S * HEAD_DIM]; // rounded V cache [g,s,d]
__device__ float g_O[S * QDIM];            // attention out (tf32-rounded)

// ----------------------------------------------------------------------------
// helpers
// ----------------------------------------------------------------------------
__device__ __forceinline__ float tf32r(float x) {
    unsigned u;
    asm("cvt.rna.tf32.f32 %0, %1;" : "=r"(u) : "f"(x));
    return __uint_as_float(u);
}

__device__ __forceinline__ void mma_tf32(float* d, const unsigned* a, const unsigned* b) {
    asm volatile(
        "mma.sync.aligned.m16n8k8.row.col.f32.tf32.tf32.f32 "
        "{%0,%1,%2,%3}, {%4,%5,%6,%7}, {%8,%9}, {%0,%1,%2,%3};"
        : "+f"(d[0]), "+f"(d[1]), "+f"(d[2]), "+f"(d[3])
        : "r"(a[0]), "r"(a[1]), "r"(a[2]), "r"(a[3]), "r"(b[0]), "r"(b[1]));
}

// ----------------------------------------------------------------------------
// Pre-round to tf32 (RNA), vectorized
// ----------------------------------------------------------------------------
__global__ void round_tf32_kernel(const float* __restrict__ src, float* __restrict__ dst,
                                  int n4) {
    int i = blockIdx.x * blockDim.x + threadIdx.x;
    if (i < n4) {
        float4 v = ((const float4*)src)[i];
        v.x = tf32r(v.x); v.y = tf32r(v.y); v.z = tf32r(v.z); v.w = tf32r(v.w);
        ((float4*)dst)[i] = v;
    }
}

// ----------------------------------------------------------------------------
// tf32 NT GEMM (round-5 proven structure, cvts removed — inputs pre-rounded):
// C[M,N] = A[M,K] @ B[N,K]^T.  BM=128 BN=64 BK=32, 256 threads (8 warps 4x2),
// warp tile 32x32, register-staged double buffering, smem stride 36.
// ldc parameterized for fused-QKV output.
// ----------------------------------------------------------------------------
#define GBM 128
#define GBN 64
#define GBK 32
#define GSTRIDE (GBK + 4)

__global__ __launch_bounds__(256) void gemm_tf32(const float* __restrict__ A,
                                                 const float* __restrict__ B,
                                                 float* __restrict__ C,
                                                 int M, int N, int K, int ldc) {
    __shared__ float As[GBM * GSTRIDE];
    __shared__ float Bs[GBN * GSTRIDE];

    const int tid = threadIdx.x;
    const int warp = tid >> 5;
    const int lane = tid & 31;
    const int wm = warp >> 1;       // 0..3
    const int wn = warp & 1;        // 0..1
    const int r = lane >> 2;        // 0..7
    const int cc = lane & 3;        // 0..3

    const int bm0 = blockIdx.y * GBM;
    const int bn0 = blockIdx.x * GBN;

    float4 ar[4], br[2];

    // stage 0 load
    {
#pragma unroll
        for (int i = 0; i < 4; i++) {
            int idx = tid + i * 256;
            int row = idx >> 3, c4 = idx & 7;
            ar[i] = *(const float4*)&A[(size_t)(bm0 + row) * K + c4 * 4];
        }
#pragma unroll
        for (int i = 0; i < 2; i++) {
            int idx = tid + i * 256;
            int row = idx >> 3, c4 = idx & 7;
            br[i] = *(const float4*)&B[(size_t)(bn0 + row) * K + c4 * 4];
        }
    }
#pragma unroll
    for (int i = 0; i < 4; i++) {
        int idx = tid + i * 256;
        int row = idx >> 3, c4 = idx & 7;
        *(float4*)&As[row * GSTRIDE + c4 * 4] = ar[i];
    }
#pragma unroll
    for (int i = 0; i < 2; i++) {
        int idx = tid + i * 256;
        int row = idx >> 3, c4 = idx & 7;
        *(float4*)&Bs[row * GSTRIDE + c4 * 4] = br[i];
    }
    __syncthreads();

    float acc[2][4][4];
#pragma unroll
    for (int mt = 0; mt < 2; mt++)
#pragma unroll
        for (int nt = 0; nt < 4; nt++)
#pragma unroll
            for (int i = 0; i < 4; i++) acc[mt][nt][i] = 0.0f;

    const int nk = K / GBK;
    for (int kt = 0; kt < nk; kt++) {
        if (kt + 1 < nk) {
            int k0 = (kt + 1) * GBK;
#pragma unroll
            for (int i = 0; i < 4; i++) {
                int idx = tid + i * 256;
                int row = idx >> 3, c4 = idx & 7;
                ar[i] = *(const float4*)&A[(size_t)(bm0 + row) * K + k0 + c4 * 4];
            }
#pragma unroll
            for (int i = 0; i < 2; i++) {
                int idx = tid + i * 256;
                int row = idx >> 3, c4 = idx & 7;
                br[i] = *(const float4*)&B[(size_t)(bn0 + row) * K + k0 + c4 * 4];
            }
        }
#pragma unroll
        for (int ks = 0; ks < 4; ks++) {
            unsigned af[2][4];
#pragma unroll
            for (int mt = 0; mt < 2; mt++) {
                int m0 = wm * 32 + mt * 16;
                af[mt][0] = __float_as_uint(As[(m0 + r) * GSTRIDE + ks * 8 + cc]);
                af[mt][1] = __float_as_uint(As[(m0 + r + 8) * GSTRIDE + ks * 8 + cc]);
                af[mt][2] = __float_as_uint(As[(m0 + r) * GSTRIDE + ks * 8 + cc + 4]);
                af[mt][3] = __float_as_uint(As[(m0 + r + 8) * GSTRIDE + ks * 8 + cc + 4]);
            }
            unsigned bf[4][2];
#pragma unroll
            for (int nt = 0; nt < 4; nt++) {
                int n0 = wn * 32 + nt * 8 + r;
                bf[nt][0] = __float_as_uint(Bs[n0 * GSTRIDE + ks * 8 + cc]);
                bf[nt][1] = __float_as_uint(Bs[n0 * GSTRIDE + ks * 8 + cc + 4]);
            }
#pragma unroll
            for (int mt = 0; mt < 2; mt++)
#pragma unroll
                for (int nt = 0; nt < 4; nt++)
                    mma_tf32(acc[mt][nt], af[mt], bf[nt]);
        }
        __syncthreads();
        if (kt + 1 < nk) {
#pragma unroll
            for (int i = 0; i < 4; i++) {
                int idx = tid + i * 256;
                int row = idx >> 3, c4 = idx & 7;
                *(float4*)&As[row * GSTRIDE + c4 * 4] = ar[i];
            }
#pragma unroll
            for (int i = 0; i < 2; i++) {
                int idx = tid + i * 256;
                int row = idx >> 3, c4 = idx & 7;
                *(float4*)&Bs[row * GSTRIDE + c4 * 4] = br[i];
            }
            __syncthreads();
        }
    }

    // epilogue
#pragma unroll
    for (int mt = 0; mt < 2; mt++) {
#pragma unroll
        for (int nt = 0; nt < 4; nt++) {
            int row = bm0 + wm * 32 + mt * 16 + r;
            int col = bn0 + wn * 32 + nt * 8 + 2 * cc;
            float2 v0 = make_float2(acc[mt][nt][0], acc[mt][nt][1]);
            float2 v1 = make_float2(acc[mt][nt][2], acc[mt][nt][3]);
            *(float2*)&C[(size_t)row * ldc + col] = v0;
            *(float2*)&C[(size_t)(row + 8) * ldc + col] = v1;
        }
    }
}

// ----------------------------------------------------------------------------
// RMSNorm + RoPE, reading from fused QKV buffer.
// Q mode: dst[s*4096 + h*128 + d] = tf32r(out).
// K mode: cache[(h*S+s)*128+d] = out (fp32 output), rdst same layout = tf32r(out).
// ----------------------------------------------------------------------------
__global__ void norm_rope_kernel(const float* __restrict__ src, float* __restrict__ dst,
                                 float* __restrict__ rdst,
                                 const float* __restrict__ w, int src_off, int dst_is_cache) {
    int s = blockIdx.x;
    int h = blockIdx.y;
    int d = threadIdx.x;

    __shared__ float sh[HEAD_DIM];
    __shared__ float red[4];

    float x = src[(size_t)s * QKVDIM + src_off + h * HEAD_DIM + d];

    float sq = x * x;
#pragma unroll
    for (int off = 16; off > 0; off >>= 1)
        sq += __shfl_down_sync(0xffffffff, sq, off);
    if ((d & 31) == 0) red[d >> 5] = sq;
    __syncthreads();
    float var = (red[0] + red[1] + red[2] + red[3]) * (1.0f / HEAD_DIM);
    float r = rsqrtf(var + EPS);
    float xn = x * r * w[d];
    sh[d] = xn;
    __syncthreads();

    int f = d & 63;
    float inv_freq = powf(ROPE_THETA, -((float)f) / 64.0f);
    float ang = (float)s * inv_freq;
    float c = cosf(ang), sn = sinf(ang);
    float out;
    if (d < 64) out = xn * c - sh[d + 64] * sn;
    else        out = xn * c + sh[d - 64] * sn;

    if (dst_is_cache) {
        size_t idx = ((size_t)h * S + s) * HEAD_DIM + d;
        dst[idx] = out;            // fp32 cache_k (problem output)
        rdst[idx] = tf32r(out);    // rounded copy for flash
    } else {
        dst[(size_t)s * QDIM + h * HEAD_DIM + d] = tf32r(out);
    }
}

// V: [s, qkv] -> cache [g, s, d] fp32 + rounded copy
__global__ void v_to_cache_kernel(const float* __restrict__ src, float* __restrict__ dst,
                                  float* __restrict__ rdst) {
    int s = blockIdx.x;
    int g = blockIdx.y;
    int d = threadIdx.x;
    float v = src[(size_t)s * QKVDIM + QDIM + KVDIM + g * HEAD_DIM + d];
    size_t idx = ((size_t)g * S + s) * HEAD_DIM + d;
    dst[idx] = v;
    rdst[idx] = tf32r(v);
}

// ----------------------------------------------------------------------------
// Flash attention with tf32 mma. All inputs pre-rounded -> no cvts in loop.
// ----------------------------------------------------------------------------
#define FQT 64
#define FKT 64
#define QS_OFF 0
#define KV_OFF 8448
#define PS_OFF 17152
#define MS_OFF 21504
#define LS_OFF 21568
#define CS_OFF 21632
#define FSMEM_FLOATS 21696

__global__ __launch_bounds__(128) void flash_tf32(const float* __restrict__ Kr,
                                                  const float* __restrict__ Vr) {
    extern __shared__ float fsm[];
    float* Qs = fsm + QS_OFF;      // stride 132
    float* KVs = fsm + KV_OFF;     // K stride 132 / V^T stride 68
    float* Ps = fsm + PS_OFF;      // stride 68
    float* mS = fsm + MS_OFF;
    float* lS = fsm + LS_OFF;
    float* corrS = fsm + CS_OFF;

    const int qTile = blockIdx.x;
    const int h = blockIdx.y;
    const int g = h >> 2;
    const int tid = threadIdx.x;
    const int warp = tid >> 5;
    const int lane = tid & 31;
    const int wm = warp >> 1;
    const int wn = warp & 1;
    const int r = lane >> 2;
    const int cc = lane & 3;
    const int qBase = qTile * FQT;
    const float scale = 0.08838834764831845f;

    if (tid < 64) { mS[tid] = -INFINITY; lS[tid] = 0.0f; }

#pragma unroll
    for (int i = 0; i < 16; i++) {
        int idx = tid + i * 128;
        int row = idx >> 5, c4 = idx & 31;
        float4 v = *(const float4*)&g_Q[(size_t)(qBase + row) * QDIM + h * HEAD_DIM + c4 * 4];
        *(float4*)&Qs[row * 132 + c4 * 4] = v;
    }

    float oacc[2][8][4];
#pragma unroll
    for (int mt = 0; mt < 2; mt++)
#pragma unroll
        for (int nt = 0; nt < 8; nt++)
#pragma unroll
            for (int i = 0; i < 4; i++) oacc[mt][nt][i] = 0.0f;

    __syncthreads();

    for (int kt = 0; kt <= qTile; kt++) {
        const int kBase = kt * FKT;

#pragma unroll
        for (int i = 0; i < 16; i++) {
            int idx = tid + i * 128;
            int row = idx >> 5, c4 = idx & 31;
            float4 v = *(const float4*)&Kr[((size_t)g * S + kBase + row) * HEAD_DIM + c4 * 4];
            *(float4*)&KVs[row * 132 + c4 * 4] = v;
        }
        __syncthreads();

        float sacc[2][4][4];
#pragma unroll
        for (int mt = 0; mt < 2; mt++)
#pragma unroll
            for (int nt = 0; nt < 4; nt++)
#pragma unroll
                for (int i = 0; i < 4; i++) sacc[mt][nt][i] = 0.0f;

#pragma unroll
        for (int ks = 0; ks < 16; ks++) {
            unsigned af[2][4];
#pragma unroll
            for (int mt = 0; mt < 2; mt++) {
                int m0 = wm * 32 + mt * 16;
                af[mt][0] = __float_as_uint(Qs[(m0 + r) * 132 + ks * 8 + cc]);
                af[mt][1] = __float_as_uint(Qs[(m0 + r + 8) * 132 + ks * 8 + cc]);
                af[mt][2] = __float_as_uint(Qs[(m0 + r) * 132 + ks * 8 + cc + 4]);
                af[mt][3] = __float_as_uint(Qs[(m0 + r + 8) * 132 + ks * 8 + cc + 4]);
            }
            unsigned bf[4][2];
#pragma unroll
            for (int nt = 0; nt < 4; nt++) {
                int n0 = wn * 32 + nt * 8 + r;
                bf[nt][0] = __float_as_uint(KVs[n0 * 132 + ks * 8 + cc]);
                bf[nt][1] = __float_as_uint(KVs[n0 * 132 + ks * 8 + cc + 4]);
            }
#pragma unroll
            for (int mt = 0; mt < 2; mt++)
#pragma unroll
                for (int nt = 0; nt < 4; nt++)
                    mma_tf32(sacc[mt][nt], af[mt], bf[nt]);
        }

#pragma unroll
        for (int mt = 0; mt < 2; mt++) {
#pragma unroll
            for (int nt = 0; nt < 4; nt++) {
                int row0 = wm * 32 + mt * 16 + r;
                int col0 = wn * 32 + nt * 8 + 2 * cc;
                int qi0 = qBase + row0, qi1 = qi0 + 8;
                int kj0 = kBase + col0, kj1 = kj0 + 1;
                Ps[row0 * 68 + col0]       = (kj0 <= qi0) ? sacc[mt][nt][0] * scale : -1e30f;
                Ps[row0 * 68 + col0 + 1]   = (kj1 <= qi0) ? sacc[mt][nt][1] * scale : -1e30f;
                Ps[(row0 + 8) * 68 + col0]     = (kj0 <= qi1) ? sacc[mt][nt][2] * scale : -1e30f;
                Ps[(row0 + 8) * 68 + col0 + 1] = (kj1 <= qi1) ? sacc[mt][nt][3] * scale : -1e30f;
            }
        }
        __syncthreads();

        // V^T load (rounded already; K no longer needed)
#pragma unroll
        for (int i = 0; i < 16; i++) {
            int idx = tid + i * 128;
            int s = idx & 63, c4 = idx >> 6;
            float4 v = *(const float4*)&Vr[((size_t)g * S + kBase + s) * HEAD_DIM + c4 * 4];
            KVs[(c4 * 4 + 0) * 68 + s] = v.x;
            KVs[(c4 * 4 + 1) * 68 + s] = v.y;
            KVs[(c4 * 4 + 2) * 68 + s] = v.z;
            KVs[(c4 * 4 + 3) * 68 + s] = v.w;
        }

        // online softmax
        {
            int row = tid >> 1;
            int half = tid & 1;
            float* prow = &Ps[row * 68 + half * 32];
            float mloc = -INFINITY;
#pragma unroll 8
            for (int j = 0; j < 32; j++) mloc = fmaxf(mloc, prow[j]);
            mloc = fmaxf(mloc, __shfl_xor_sync(0xffffffffu, mloc, 1));
            float mprev = mS[row];
            float mnew = fmaxf(mprev, mloc);
            float lsum = 0.0f;
#pragma unroll 8
            for (int j = 0; j < 32; j++) {
                float p = __expf(prow[j] - mnew);
                lsum += p;
                prow[j] = tf32r(p);
            }
            lsum += __shfl_xor_sync(0xffffffffu, lsum, 1);
            if (half == 0) {
                float corr = __expf(mprev - mnew);
                corrS[row] = corr;
                lS[row] = lS[row] * corr + lsum;
                mS[row] = mnew;
            }
        }
        __syncthreads();

#pragma unroll
        for (int mt = 0; mt < 2; mt++) {
            int row0 = wm * 32 + mt * 16 + r;
            float cr0 = corrS[row0];
            float cr1 = corrS[row0 + 8];
#pragma unroll
            for (int nt = 0; nt < 8; nt++) {
                oacc[mt][nt][0] *= cr0; oacc[mt][nt][1] *= cr0;
                oacc[mt][nt][2] *= cr1; oacc[mt][nt][3] *= cr1;
            }
        }

#pragma unroll
        for (int ks = 0; ks < 8; ks++) {
            unsigned af[2][4];
#pragma unroll
            for (int mt = 0; mt < 2; mt++) {
                int m0 = wm * 32 + mt * 16;
                af[mt][0] = __float_as_uint(Ps[(m0 + r) * 68 + ks * 8 + cc]);
                af[mt][1] = __float_as_uint(Ps[(m0 + r + 8) * 68 + ks * 8 + cc]);
                af[mt][2] = __float_as_uint(Ps[(m0 + r) * 68 + ks * 8 + cc + 4]);
                af[mt][3] = __float_as_uint(Ps[(m0 + r + 8) * 68 + ks * 8 + cc + 4]);
            }
#pragma unroll
            for (int nt = 0; nt < 8; nt++) {
                int n0 = wn * 64 + nt * 8 + r;
                unsigned bf[2];
                bf[0] = __float_as_uint(KVs[n0 * 68 + ks * 8 + cc]);
                bf[1] = __float_as_uint(KVs[n0 * 68 + ks * 8 + cc + 4]);
#pragma unroll
                for (int mt = 0; mt < 2; mt++)
                    mma_tf32(oacc[mt][nt], af[mt], bf);
            }
        }
        __syncthreads();
    }

    // epilogue: normalize, round (feeds final GEMM), write
#pragma unroll
    for (int mt = 0; mt < 2; mt++) {
        int row0 = wm * 32 + mt * 16 + r;
        float li0 = 1.0f / lS[row0];
        float li1 = 1.0f / lS[row0 + 8];
#pragma unroll
        for (int nt = 0; nt < 8; nt++) {
            int col = wn * 64 + nt * 8 + 2 * cc;
            float2 v0 = make_float2(tf32r(oacc[mt][nt][0] * li0), tf32r(oacc[mt][nt][1] * li0));
            float2 v1 = make_float2(tf32r(oacc[mt][nt][2] * li1), tf32r(oacc[mt][nt][3] * li1));
            *(float2*)&g_O[(size_t)(qBase + row0) * QDIM + h * HEAD_DIM + col] = v0;
            *(float2*)&g_O[(size_t)(qBase + row0 + 8) * QDIM + h * HEAD_DIM + col] = v1;
        }
    }
}

// ----------------------------------------------------------------------------
extern "C" void kernel_launch(void* const* d_in, const int* in_sizes, int n_in,
                              void* d_out, int out_size) {
    const float* x  = (const float*)d_in[0];
    const float* Wq = (const float*)d_in[1];
    const float* Wk = (const float*)d_in[2];
    const float* Wv = (const float*)d_in[3];
    const float* Wo = (const float*)d_in[4];
    const float* qw = (const float*)d_in[5];
    const float* kw = (const float*)d_in[6];

    float* out    = (float*)d_out;
    float* cacheK = out + (size_t)S * D_MODEL;
    float* cacheV = cacheK + (size_t)NUM_KV_HEADS * S * HEAD_DIM;

    float* dX;    cudaGetSymbolAddress((void**)&dX, g_X);
    float* dWqkv; cudaGetSymbolAddress((void**)&dWqkv, g_Wqkv);
    float* dWo;   cudaGetSymbolAddress((void**)&dWo, g_Wo);
    float* dQKV;  cudaGetSymbolAddress((void**)&dQKV, g_QKV);
    float* dQ;    cudaGetSymbolAddress((void**)&dQ, g_Q);
    float* dKr;   cudaGetSymbolAddress((void**)&dKr, g_Kr);
    float* dVr;   cudaGetSymbolAddress((void**)&dVr, g_Vr);
    float* dO;    cudaGetSymbolAddress((void**)&dO, g_O);

    // 0) pre-round inputs to tf32 (RNA) once
    {
        int n;
        n = S * D_MODEL / 4;
        round_tf32_kernel<<<(n + 255) / 256, 256>>>(x, dX, n);
        n = QDIM * D_MODEL / 4;
        round_tf32_kernel<<<(n + 255) / 256, 256>>>(Wq, dWqkv, n);
        n = KVDIM * D_MODEL / 4;
        round_tf32_kernel<<<(n + 255) / 256, 256>>>(Wk, dWqkv + (size_t)QDIM * D_MODEL, n);
        round_tf32_kernel<<<(n + 255) / 256, 256>>>(Wv, dWqkv + (size_t)(QDIM + KVDIM) * D_MODEL, n);
        n = D_MODEL * QDIM / 4;
        round_tf32_kernel<<<(n + 255) / 256, 256>>>(Wo, dWo, n);
    }

    // 1) fused QKV projection: [2048, 6144] = X @ [Wq;Wk;Wv]^T
    gemm_tf32<<<dim3(QKVDIM / GBN, S / GBM), 256>>>(dX, dWqkv, dQKV, S, QKVDIM, D_MODEL, QKVDIM);

    // 2) RMSNorm + RoPE (Q -> g_Q rounded; K -> cache fp32 + rounded), V -> cache + rounded
    norm_rope_kernel<<<dim3(S, NUM_HEADS), HEAD_DIM>>>(dQKV, dQ, dQ, qw, 0, 0);
    norm_rope_kernel<<<dim3(S, NUM_KV_HEADS), HEAD_DIM>>>(dQKV, cacheK, dKr, kw, QDIM, 1);
    v_to_cache_kernel<<<dim3(S, NUM_KV_HEADS), HEAD_DIM>>>(dQKV, cacheV, dVr);

    // 3) Flash attention (tf32 mma, pre-rounded K/V)
    {
        size_t smem_bytes = FSMEM_FLOATS * sizeof(float); // 86784
        cudaFuncSetAttribute(flash_tf32, cudaFuncAttributeMaxDynamicSharedMemorySize,
                             (int)smem_bytes);
        flash_tf32<<<dim3(S / FQT, NUM_HEADS), 128, smem_bytes>>>(dKr, dVr);
    }

    // 4) Output projection: out = O @ Wo^T
    gemm_tf32<<<dim3(D_MODEL / GBN, S / GBM), 256>>>(dO, dWo, out, S, D_MODEL, QDIM, D_MODEL);
}

// round 9
// speedup vs baseline: 1.5362x; 1.2103x over previous
#include <cuda_runtime.h>
#include <cuda_bf16.h>
#include <math.h>
#include <stdint.h>

// Problem constants
#define S 2048
#define D_MODEL 2560
#define NUM_HEADS 32
#define NUM_KV_HEADS 8
#define HEAD_DIM 128
#define QDIM (NUM_HEADS * HEAD_DIM)     // 4096
#define KVDIM (NUM_KV_HEADS * HEAD_DIM) // 1024
#define QKVDIM (QDIM + 2 * KVDIM)       // 6144
#define EPS 1e-6f
#define ROPE_THETA 5000000.0f

// Scratch (no allocs allowed -> __device__ globals)
__device__ float g_X[S * D_MODEL];         // tf32-rounded x
__device__ float g_Wqkv[QKVDIM * D_MODEL]; // tf32-rounded [Wq;Wk;Wv]
__device__ float g_Wo[D_MODEL * QDIM];     // tf32-rounded Wo
__device__ float g_QKV[S * QKVDIM];        // raw qkv projections
__device__ float g_Q[S * QDIM];            // normed+roped Q (tf32-rounded)
__device__ float g_Kr[NUM_KV_HEADS * S * HEAD_DIM]; // rounded K cache [g,s,d]
__device__ float g_Vr[NUM_KV_HEADS * S * HEAD_DIM]; // rounded V cache [g,s,d]
__device__ float g_O[S * QDIM];            // attention out (tf32-rounded)

// ----------------------------------------------------------------------------
// helpers
// ----------------------------------------------------------------------------
__device__ __forceinline__ float tf32r(float x) {
    unsigned u;
    asm("cvt.rna.tf32.f32 %0, %1;" : "=r"(u) : "f"(x));
    return __uint_as_float(u);
}

__device__ __forceinline__ void mma_tf32(float* d, const unsigned* a, const unsigned* b) {
    asm volatile(
        "mma.sync.aligned.m16n8k8.row.col.f32.tf32.tf32.f32 "
        "{%0,%1,%2,%3}, {%4,%5,%6,%7}, {%8,%9}, {%0,%1,%2,%3};"
        : "+f"(d[0]), "+f"(d[1]), "+f"(d[2]), "+f"(d[3])
        : "r"(a[0]), "r"(a[1]), "r"(a[2]), "r"(a[3]), "r"(b[0]), "r"(b[1]));
}

__device__ __forceinline__ void cp_async16(void* smem_dst, const void* gmem_src) {
    unsigned saddr = (unsigned)__cvta_generic_to_shared(smem_dst);
    asm volatile("cp.async.cg.shared.global [%0], [%1], 16;" :: "r"(saddr), "l"(gmem_src));
}
#define CP_COMMIT() asm volatile("cp.async.commit_group;")

// ----------------------------------------------------------------------------
// Fused pre-round of all inputs to tf32 (RNA). One launch.
// Ranges in float4 units: X | Wq | Wk | Wv | Wo
// ----------------------------------------------------------------------------
#define R_N1 (S * D_MODEL / 4)          // 1310720
#define R_N2 (QDIM * D_MODEL / 4)       // 2621440
#define R_N3 (KVDIM * D_MODEL / 4)      // 655360
#define R_TOT (R_N1 + R_N2 + 2 * R_N3 + R_N2) // 7864320

__global__ void round_all_kernel(const float* __restrict__ x,
                                 const float* __restrict__ Wq,
                                 const float* __restrict__ Wk,
                                 const float* __restrict__ Wv,
                                 const float* __restrict__ Wo) {
    long i = (long)blockIdx.x * blockDim.x + threadIdx.x;
    if (i >= R_TOT) return;
    const float4* src;
    float4* dst;
    if (i < R_N1) {
        src = (const float4*)x;
        dst = (float4*)g_X;
    } else if (i < R_N1 + R_N2) {
        i -= R_N1;
        src = (const float4*)Wq;
        dst = (float4*)g_Wqkv;
    } else if (i < R_N1 + R_N2 + R_N3) {
        i -= R_N1 + R_N2;
        src = (const float4*)Wk;
        dst = (float4*)(g_Wqkv + (size_t)QDIM * D_MODEL);
    } else if (i < R_N1 + R_N2 + 2 * R_N3) {
        i -= R_N1 + R_N2 + R_N3;
        src = (const float4*)Wv;
        dst = (float4*)(g_Wqkv + (size_t)(QDIM + KVDIM) * D_MODEL);
    } else {
        i -= R_N1 + R_N2 + 2 * R_N3;
        src = (const float4*)Wo;
        dst = (float4*)g_Wo;
    }
    float4 v = src[i];
    v.x = tf32r(v.x); v.y = tf32r(v.y); v.z = tf32r(v.z); v.w = tf32r(v.w);
    dst[i] = v;
}

// ----------------------------------------------------------------------------
// tf32 NT GEMM v3: C[M,N] = A[M,K] @ B[N,K]^T, inputs pre-rounded tf32.
// Block 128x64, 128 threads (4 warps, each 32x64 -> 1.5 LDS per mma).
// 2-stage cp.async double buffer (55 KB smem -> 4 CTA/SM).
// Per-element k accumulation order identical to previous rounds.
// ----------------------------------------------------------------------------
#define BM3 128
#define BN3 64
#define BK3 32
#define ST3 36
#define STG3 ((BM3 + BN3) * ST3)        // 6912 floats per stage
#define G3_SMEM (2 * STG3 * 4)          // 55296 B

__global__ __launch_bounds__(128) void gemm_tf32_v3(const float* __restrict__ A,
                                                    const float* __restrict__ B,
                                                    float* __restrict__ C,
                                                    int M, int N, int K, int ldc) {
    extern __shared__ float sm3[];

    const int tid = threadIdx.x;
    const int warp = tid >> 5;      // 0..3 -> rows warp*32..+32
    const int lane = tid & 31;
    const int r = lane >> 2;        // 0..7
    const int cc = lane & 3;        // 0..3
    const int bm0 = blockIdx.y * BM3;
    const int bn0 = blockIdx.x * BN3;
    const int nk = K / BK3;

    auto issue = [&](int kt) {
        float* As = sm3 + (kt & 1) * STG3;
        float* Bs = As + BM3 * ST3;
        const int k0 = kt * BK3;
#pragma unroll
        for (int i = 0; i < 8; i++) {      // A: 128 rows x 8 chunks / 128 thr
            int task = tid + i * 128;
            int row = task >> 3, ch = task & 7;
            cp_async16(&As[row * ST3 + ch * 4],
                       &A[(size_t)(bm0 + row) * K + k0 + ch * 4]);
        }
#pragma unroll
        for (int i = 0; i < 4; i++) {      // B: 64 rows x 8 chunks / 128 thr
            int task = tid + i * 128;
            int row = task >> 3, ch = task & 7;
            cp_async16(&Bs[row * ST3 + ch * 4],
                       &B[(size_t)(bn0 + row) * K + k0 + ch * 4]);
        }
        CP_COMMIT();
    };

    issue(0);
    if (nk > 1) issue(1);

    float acc[2][8][4];
#pragma unroll
    for (int mt = 0; mt < 2; mt++)
#pragma unroll
        for (int nt = 0; nt < 8; nt++)
#pragma unroll
            for (int i = 0; i < 4; i++) acc[mt][nt][i] = 0.0f;

    for (int kt = 0; kt < nk; kt++) {
        if (kt == nk - 1) asm volatile("cp.async.wait_group 0;" ::: "memory");
        else              asm volatile("cp.async.wait_group 1;" ::: "memory");
        __syncthreads();

        const float* As = sm3 + (kt & 1) * STG3;
        const float* Bs = As + BM3 * ST3;

#pragma unroll
        for (int ks = 0; ks < 4; ks++) {
            unsigned af[2][4];
#pragma unroll
            for (int mt = 0; mt < 2; mt++) {
                int m0 = warp * 32 + mt * 16;
                af[mt][0] = __float_as_uint(As[(m0 + r) * ST3 + ks * 8 + cc]);
                af[mt][1] = __float_as_uint(As[(m0 + r + 8) * ST3 + ks * 8 + cc]);
                af[mt][2] = __float_as_uint(As[(m0 + r) * ST3 + ks * 8 + cc + 4]);
                af[mt][3] = __float_as_uint(As[(m0 + r + 8) * ST3 + ks * 8 + cc + 4]);
            }
            unsigned bf[8][2];
#pragma unroll
            for (int nt = 0; nt < 8; nt++) {
                int n0 = nt * 8 + r;
                bf[nt][0] = __float_as_uint(Bs[n0 * ST3 + ks * 8 + cc]);
                bf[nt][1] = __float_as_uint(Bs[n0 * ST3 + ks * 8 + cc + 4]);
            }
#pragma unroll
            for (int mt = 0; mt < 2; mt++)
#pragma unroll
                for (int nt = 0; nt < 8; nt++)
                    mma_tf32(acc[mt][nt], af[mt], bf[nt]);
        }
        __syncthreads();
        if (kt + 2 < nk) issue(kt + 2);
    }

    // epilogue
#pragma unroll
    for (int mt = 0; mt < 2; mt++) {
#pragma unroll
        for (int nt = 0; nt < 8; nt++) {
            int row = bm0 + warp * 32 + mt * 16 + r;
            int col = bn0 + nt * 8 + 2 * cc;
            float2 v0 = make_float2(acc[mt][nt][0], acc[mt][nt][1]);
            float2 v1 = make_float2(acc[mt][nt][2], acc[mt][nt][3]);
            *(float2*)&C[(size_t)row * ldc + col] = v0;
            *(float2*)&C[(size_t)(row + 8) * ldc + col] = v1;
        }
    }
}

// ----------------------------------------------------------------------------
// RMSNorm + RoPE for Q (writes g_Q tf32-rounded)
// ----------------------------------------------------------------------------
__global__ void norm_rope_q_kernel(const float* __restrict__ src, float* __restrict__ dst,
                                   const float* __restrict__ w) {
    int s = blockIdx.x;
    int h = blockIdx.y;
    int d = threadIdx.x;

    __shared__ float sh[HEAD_DIM];
    __shared__ float red[4];

    float x = src[(size_t)s * QKVDIM + h * HEAD_DIM + d];

    float sq = x * x;
#pragma unroll
    for (int off = 16; off > 0; off >>= 1)
        sq += __shfl_down_sync(0xffffffff, sq, off);
    if ((d & 31) == 0) red[d >> 5] = sq;
    __syncthreads();
    float var = (red[0] + red[1] + red[2] + red[3]) * (1.0f / HEAD_DIM);
    float r = rsqrtf(var + EPS);
    float xn = x * r * w[d];
    sh[d] = xn;
    __syncthreads();

    int f = d & 63;
    float inv_freq = powf(ROPE_THETA, -((float)f) / 64.0f);
    float ang = (float)s * inv_freq;
    float c = cosf(ang), sn = sinf(ang);
    float out;
    if (d < 64) out = xn * c - sh[d + 64] * sn;
    else        out = xn * c + sh[d - 64] * sn;

    dst[(size_t)s * QDIM + h * HEAD_DIM + d] = tf32r(out);
}

// ----------------------------------------------------------------------------
// RMSNorm + RoPE for K (-> cache_k fp32 + g_Kr rounded) AND V copy
// (-> cache_v fp32 + g_Vr rounded). One launch, grid (S, 8), block 128.
// ----------------------------------------------------------------------------
__global__ void norm_rope_kv_kernel(const float* __restrict__ src,
                                    float* __restrict__ cacheK, float* __restrict__ Kr,
                                    float* __restrict__ cacheV, float* __restrict__ Vr,
                                    const float* __restrict__ w) {
    int s = blockIdx.x;
    int h = blockIdx.y;      // kv head
    int d = threadIdx.x;

    __shared__ float sh[HEAD_DIM];
    __shared__ float red[4];

    float x = src[(size_t)s * QKVDIM + QDIM + h * HEAD_DIM + d];

    float sq = x * x;
#pragma unroll
    for (int off = 16; off > 0; off >>= 1)
        sq += __shfl_down_sync(0xffffffff, sq, off);
    if ((d & 31) == 0) red[d >> 5] = sq;
    __syncthreads();
    float var = (red[0] + red[1] + red[2] + red[3]) * (1.0f / HEAD_DIM);
    float r = rsqrtf(var + EPS);
    float xn = x * r * w[d];
    sh[d] = xn;
    __syncthreads();

    int f = d & 63;
    float inv_freq = powf(ROPE_THETA, -((float)f) / 64.0f);
    float ang = (float)s * inv_freq;
    float c = cosf(ang), sn = sinf(ang);
    float out;
    if (d < 64) out = xn * c - sh[d + 64] * sn;
    else        out = xn * c + sh[d - 64] * sn;

    size_t idx = ((size_t)h * S + s) * HEAD_DIM + d;
    cacheK[idx] = out;
    Kr[idx] = tf32r(out);

    // V copy (independent of the norm work above)
    float v = src[(size_t)s * QKVDIM + QDIM + KVDIM + h * HEAD_DIM + d];
    cacheV[idx] = v;
    Vr[idx] = tf32r(v);
}

// ----------------------------------------------------------------------------
// Flash attention with tf32 mma (unchanged; inputs pre-rounded).
// ----------------------------------------------------------------------------
#define FQT 64
#define FKT 64
#define QS_OFF 0
#define KV_OFF 8448
#define PS_OFF 17152
#define MS_OFF 21504
#define LS_OFF 21568
#define CS_OFF 21632
#define FSMEM_FLOATS 21696

__global__ __launch_bounds__(128) void flash_tf32(const float* __restrict__ Kr,
                                                  const float* __restrict__ Vr) {
    extern __shared__ float fsm[];
    float* Qs = fsm + QS_OFF;
    float* KVs = fsm + KV_OFF;
    float* Ps = fsm + PS_OFF;
    float* mS = fsm + MS_OFF;
    float* lS = fsm + LS_OFF;
    float* corrS = fsm + CS_OFF;

    const int qTile = blockIdx.x;
    const int h = blockIdx.y;
    const int g = h >> 2;
    const int tid = threadIdx.x;
    const int warp = tid >> 5;
    const int lane = tid & 31;
    const int wm = warp >> 1;
    const int wn = warp & 1;
    const int r = lane >> 2;
    const int cc = lane & 3;
    const int qBase = qTile * FQT;
    const float scale = 0.08838834764831845f;

    if (tid < 64) { mS[tid] = -INFINITY; lS[tid] = 0.0f; }

#pragma unroll
    for (int i = 0; i < 16; i++) {
        int idx = tid + i * 128;
        int row = idx >> 5, c4 = idx & 31;
        float4 v = *(const float4*)&g_Q[(size_t)(qBase + row) * QDIM + h * HEAD_DIM + c4 * 4];
        *(float4*)&Qs[row * 132 + c4 * 4] = v;
    }

    float oacc[2][8][4];
#pragma unroll
    for (int mt = 0; mt < 2; mt++)
#pragma unroll
        for (int nt = 0; nt < 8; nt++)
#pragma unroll
            for (int i = 0; i < 4; i++) oacc[mt][nt][i] = 0.0f;

    __syncthreads();

    for (int kt = 0; kt <= qTile; kt++) {
        const int kBase = kt * FKT;

#pragma unroll
        for (int i = 0; i < 16; i++) {
            int idx = tid + i * 128;
            int row = idx >> 5, c4 = idx & 31;
            float4 v = *(const float4*)&Kr[((size_t)g * S + kBase + row) * HEAD_DIM + c4 * 4];
            *(float4*)&KVs[row * 132 + c4 * 4] = v;
        }
        __syncthreads();

        float sacc[2][4][4];
#pragma unroll
        for (int mt = 0; mt < 2; mt++)
#pragma unroll
            for (int nt = 0; nt < 4; nt++)
#pragma unroll
                for (int i = 0; i < 4; i++) sacc[mt][nt][i] = 0.0f;

#pragma unroll
        for (int ks = 0; ks < 16; ks++) {
            unsigned af[2][4];
#pragma unroll
            for (int mt = 0; mt < 2; mt++) {
                int m0 = wm * 32 + mt * 16;
                af[mt][0] = __float_as_uint(Qs[(m0 + r) * 132 + ks * 8 + cc]);
                af[mt][1] = __float_as_uint(Qs[(m0 + r + 8) * 132 + ks * 8 + cc]);
                af[mt][2] = __float_as_uint(Qs[(m0 + r) * 132 + ks * 8 + cc + 4]);
                af[mt][3] = __float_as_uint(Qs[(m0 + r + 8) * 132 + ks * 8 + cc + 4]);
            }
            unsigned bf[4][2];
#pragma unroll
            for (int nt = 0; nt < 4; nt++) {
                int n0 = wn * 32 + nt * 8 + r;
                bf[nt][0] = __float_as_uint(KVs[n0 * 132 + ks * 8 + cc]);
                bf[nt][1] = __float_as_uint(KVs[n0 * 132 + ks * 8 + cc + 4]);
            }
#pragma unroll
            for (int mt = 0; mt < 2; mt++)
#pragma unroll
                for (int nt = 0; nt < 4; nt++)
                    mma_tf32(sacc[mt][nt], af[mt], bf[nt]);
        }

#pragma unroll
        for (int mt = 0; mt < 2; mt++) {
#pragma unroll
            for (int nt = 0; nt < 4; nt++) {
                int row0 = wm * 32 + mt * 16 + r;
                int col0 = wn * 32 + nt * 8 + 2 * cc;
                int qi0 = qBase + row0, qi1 = qi0 + 8;
                int kj0 = kBase + col0, kj1 = kj0 + 1;
                Ps[row0 * 68 + col0]       = (kj0 <= qi0) ? sacc[mt][nt][0] * scale : -1e30f;
                Ps[row0 * 68 + col0 + 1]   = (kj1 <= qi0) ? sacc[mt][nt][1] * scale : -1e30f;
                Ps[(row0 + 8) * 68 + col0]     = (kj0 <= qi1) ? sacc[mt][nt][2] * scale : -1e30f;
                Ps[(row0 + 8) * 68 + col0 + 1] = (kj1 <= qi1) ? sacc[mt][nt][3] * scale : -1e30f;
            }
        }
        __syncthreads();

#pragma unroll
        for (int i = 0; i < 16; i++) {
            int idx = tid + i * 128;
            int s = idx & 63, c4 = idx >> 6;
            float4 v = *(const float4*)&Vr[((size_t)g * S + kBase + s) * HEAD_DIM + c4 * 4];
            KVs[(c4 * 4 + 0) * 68 + s] = v.x;
            KVs[(c4 * 4 + 1) * 68 + s] = v.y;
            KVs[(c4 * 4 + 2) * 68 + s] = v.z;
            KVs[(c4 * 4 + 3) * 68 + s] = v.w;
        }

        {
            int row = tid >> 1;
            int half = tid & 1;
            float* prow = &Ps[row * 68 + half * 32];
            float mloc = -INFINITY;
#pragma unroll 8
            for (int j = 0; j < 32; j++) mloc = fmaxf(mloc, prow[j]);
            mloc = fmaxf(mloc, __shfl_xor_sync(0xffffffffu, mloc, 1));
            float mprev = mS[row];
            float mnew = fmaxf(mprev, mloc);
            float lsum = 0.0f;
#pragma unroll 8
            for (int j = 0; j < 32; j++) {
                float p = __expf(prow[j] - mnew);
                lsum += p;
                prow[j] = tf32r(p);
            }
            lsum += __shfl_xor_sync(0xffffffffu, lsum, 1);
            if (half == 0) {
                float corr = __expf(mprev - mnew);
                corrS[row] = corr;
                lS[row] = lS[row] * corr + lsum;
                mS[row] = mnew;
            }
        }
        __syncthreads();

#pragma unroll
        for (int mt = 0; mt < 2; mt++) {
            int row0 = wm * 32 + mt * 16 + r;
            float cr0 = corrS[row0];
            float cr1 = corrS[row0 + 8];
#pragma unroll
            for (int nt = 0; nt < 8; nt++) {
                oacc[mt][nt][0] *= cr0; oacc[mt][nt][1] *= cr0;
                oacc[mt][nt][2] *= cr1; oacc[mt][nt][3] *= cr1;
            }
        }

#pragma unroll
        for (int ks = 0; ks < 8; ks++) {
            unsigned af[2][4];
#pragma unroll
            for (int mt = 0; mt < 2; mt++) {
                int m0 = wm * 32 + mt * 16;
                af[mt][0] = __float_as_uint(Ps[(m0 + r) * 68 + ks * 8 + cc]);
                af[mt][1] = __float_as_uint(Ps[(m0 + r + 8) * 68 + ks * 8 + cc]);
                af[mt][2] = __float_as_uint(Ps[(m0 + r) * 68 + ks * 8 + cc + 4]);
                af[mt][3] = __float_as_uint(Ps[(m0 + r + 8) * 68 + ks * 8 + cc + 4]);
            }
#pragma unroll
            for (int nt = 0; nt < 8; nt++) {
                int n0 = wn * 64 + nt * 8 + r;
                unsigned bf[2];
                bf[0] = __float_as_uint(KVs[n0 * 68 + ks * 8 + cc]);
                bf[1] = __float_as_uint(KVs[n0 * 68 + ks * 8 + cc + 4]);
#pragma unroll
                for (int mt = 0; mt < 2; mt++)
                    mma_tf32(oacc[mt][nt], af[mt], bf);
            }
        }
        __syncthreads();
    }

#pragma unroll
    for (int mt = 0; mt < 2; mt++) {
        int row0 = wm * 32 + mt * 16 + r;
        float li0 = 1.0f / lS[row0];
        float li1 = 1.0f / lS[row0 + 8];
#pragma unroll
        for (int nt = 0; nt < 8; nt++) {
            int col = wn * 64 + nt * 8 + 2 * cc;
            float2 v0 = make_float2(tf32r(oacc[mt][nt][0] * li0), tf32r(oacc[mt][nt][1] * li0));
            float2 v1 = make_float2(tf32r(oacc[mt][nt][2] * li1), tf32r(oacc[mt][nt][3] * li1));
            *(float2*)&g_O[(size_t)(qBase + row0) * QDIM + h * HEAD_DIM + col] = v0;
            *(float2*)&g_O[(size_t)(qBase + row0 + 8) * QDIM + h * HEAD_DIM + col] = v1;
        }
    }
}

// ----------------------------------------------------------------------------
extern "C" void kernel_launch(void* const* d_in, const int* in_sizes, int n_in,
                              void* d_out, int out_size) {
    const float* x  = (const float*)d_in[0];
    const float* Wq = (const float*)d_in[1];
    const float* Wk = (const float*)d_in[2];
    const float* Wv = (const float*)d_in[3];
    const float* Wo = (const float*)d_in[4];
    const float* qw = (const float*)d_in[5];
    const float* kw = (const float*)d_in[6];

    float* out    = (float*)d_out;
    float* cacheK = out + (size_t)S * D_MODEL;
    float* cacheV = cacheK + (size_t)NUM_KV_HEADS * S * HEAD_DIM;

    float* dX;    cudaGetSymbolAddress((void**)&dX, g_X);
    float* dWqkv; cudaGetSymbolAddress((void**)&dWqkv, g_Wqkv);
    float* dWo;   cudaGetSymbolAddress((void**)&dWo, g_Wo);
    float* dQKV;  cudaGetSymbolAddress((void**)&dQKV, g_QKV);
    float* dQ;    cudaGetSymbolAddress((void**)&dQ, g_Q);
    float* dKr;   cudaGetSymbolAddress((void**)&dKr, g_Kr);
    float* dVr;   cudaGetSymbolAddress((void**)&dVr, g_Vr);
    float* dO;    cudaGetSymbolAddress((void**)&dO, g_O);

    cudaFuncSetAttribute(gemm_tf32_v3, cudaFuncAttributeMaxDynamicSharedMemorySize, G3_SMEM);

    // (1) pre-round all inputs to tf32, one launch
    round_all_kernel<<<(R_TOT + 255) / 256, 256>>>(x, Wq, Wk, Wv, Wo);

    // (2) fused QKV projection: [2048, 6144] = X @ [Wq;Wk;Wv]^T
    gemm_tf32_v3<<<dim3(QKVDIM / BN3, S / BM3), 128, G3_SMEM>>>(
        dX, dWqkv, dQKV, S, QKVDIM, D_MODEL, QKVDIM);

    // (3) Q norm+rope -> g_Q rounded
    norm_rope_q_kernel<<<dim3(S, NUM_HEADS), HEAD_DIM>>>(dQKV, dQ, qw);

    // (4) K norm+rope -> cache_k fp32 + g_Kr, V -> cache_v fp32 + g_Vr
    norm_rope_kv_kernel<<<dim3(S, NUM_KV_HEADS), HEAD_DIM>>>(
        dQKV, cacheK, dKr, cacheV, dVr, kw);

    // (5) Flash attention (profiled launch)
    {
        size_t smem_bytes = FSMEM_FLOATS * sizeof(float); // 86784
        cudaFuncSetAttribute(flash_tf32, cudaFuncAttributeMaxDynamicSharedMemorySize,
                             (int)smem_bytes);
        flash_tf32<<<dim3(S / FQT, NUM_HEADS), 128, smem_bytes>>>(dKr, dVr);
    }

    // (6) Output projection: out = O @ Wo^T
    gemm_tf32_v3<<<dim3(D_MODEL / BN3, S / BM3), 128, G3_SMEM>>>(
        dO, dWo, out, S, D_MODEL, QDIM, D_MODEL);
}

// round 10
// speedup vs baseline: 2.4447x; 1.5914x over previous
#include <cuda_runtime.h>
#include <cuda_fp16.h>
#include <math.h>
#include <stdint.h>

// Problem constants
#define S 2048
#define D_MODEL 2560
#define NUM_HEADS 32
#define NUM_KV_HEADS 8
#define HEAD_DIM 128
#define QDIM (NUM_HEADS * HEAD_DIM)     // 4096
#define KVDIM (NUM_KV_HEADS * HEAD_DIM) // 1024
#define QKVDIM (QDIM + 2 * KVDIM)       // 6144
#define EPS 1e-6f
#define ROPE_THETA 5000000.0f

// Scratch (no allocs allowed -> __device__ globals)
__device__ __half g_Xh[S * D_MODEL];          // fp16 x
__device__ __half g_Wqkvh[QKVDIM * D_MODEL];  // fp16 [Wq;Wk;Wv]
__device__ __half g_Woh[D_MODEL * QDIM];      // fp16 Wo
__device__ float  g_QKV[S * QKVDIM];          // fp32 qkv projections
__device__ __half g_Qh[S * QDIM];             // fp16 normed+roped Q
__device__ __half g_Krh[NUM_KV_HEADS * S * HEAD_DIM]; // fp16 K cache [g,s,d]
__device__ __half g_Vrh[NUM_KV_HEADS * S * HEAD_DIM]; // fp16 V cache [g,s,d]
__device__ __half g_Oh[S * QDIM];             // fp16 attention out

// ----------------------------------------------------------------------------
// helpers
// ----------------------------------------------------------------------------
__device__ __forceinline__ void mma_f16(float* d, const unsigned* a, const unsigned* b) {
    asm volatile(
        "mma.sync.aligned.m16n8k16.row.col.f32.f16.f16.f32 "
        "{%0,%1,%2,%3}, {%4,%5,%6,%7}, {%8,%9}, {%0,%1,%2,%3};"
        : "+f"(d[0]), "+f"(d[1]), "+f"(d[2]), "+f"(d[3])
        : "r"(a[0]), "r"(a[1]), "r"(a[2]), "r"(a[3]), "r"(b[0]), "r"(b[1]));
}

__device__ __forceinline__ void cp_async16(void* smem_dst, const void* gmem_src) {
    unsigned saddr = (unsigned)__cvta_generic_to_shared(smem_dst);
    asm volatile("cp.async.cg.shared.global [%0], [%1], 16;" :: "r"(saddr), "l"(gmem_src));
}
#define CP_COMMIT() asm volatile("cp.async.commit_group;")

// ----------------------------------------------------------------------------
// Fused pre-round of all inputs to fp16 (RNE). One launch.
// Each thread handles one float4 -> 4 halfs.
// ----------------------------------------------------------------------------
#define R_N1 (S * D_MODEL / 4)
#define R_N2 (QDIM * D_MODEL / 4)
#define R_N3 (KVDIM * D_MODEL / 4)
#define R_TOT (R_N1 + R_N2 + 2 * R_N3 + R_N2)

__global__ void round_all_kernel(const float* __restrict__ x,
                                 const float* __restrict__ Wq,
                                 const float* __restrict__ Wk,
                                 const float* __restrict__ Wv,
                                 const float* __restrict__ Wo) {
    long i = (long)blockIdx.x * blockDim.x + threadIdx.x;
    if (i >= R_TOT) return;
    const float4* src;
    __half* dst;
    if (i < R_N1) {
        src = (const float4*)x;
        dst = g_Xh;
    } else if (i < R_N1 + R_N2) {
        i -= R_N1;
        src = (const float4*)Wq;
        dst = g_Wqkvh;
    } else if (i < R_N1 + R_N2 + R_N3) {
        i -= R_N1 + R_N2;
        src = (const float4*)Wk;
        dst = g_Wqkvh + (size_t)QDIM * D_MODEL;
    } else if (i < R_N1 + R_N2 + 2 * R_N3) {
        i -= R_N1 + R_N2 + R_N3;
        src = (const float4*)Wv;
        dst = g_Wqkvh + (size_t)(QDIM + KVDIM) * D_MODEL;
    } else {
        i -= R_N1 + R_N2 + 2 * R_N3;
        src = (const float4*)Wo;
        dst = g_Woh;
    }
    float4 v = src[i];
    __half2 h0 = __floats2half2_rn(v.x, v.y);
    __half2 h1 = __floats2half2_rn(v.z, v.w);
    uint2 pk = make_uint2(*(unsigned*)&h0, *(unsigned*)&h1);
    *(uint2*)&dst[i * 4] = pk;
}

// ----------------------------------------------------------------------------
// fp16 NT GEMM: C[M,N] = A[M,K] @ B[N,K]^T, A/B fp16, C fp32.
// Block 128x64, 128 threads (4 warps, warp tile 32x64), mma m16n8k16.
// BK=64 halfs; 2-stage cp.async; row stride 72 halfs (36 half2, ==4 mod 32).
// ----------------------------------------------------------------------------
#define BM4 128
#define BN4 64
#define BK4 64                  // halfs per k-chunk
#define ST4 36                  // half2 per row
#define STG4_B ((BM4 + BN4) * ST4 * 4)   // bytes per stage: 192*144 = 27648
#define G4_SMEM (2 * STG4_B)             // 55296

__global__ __launch_bounds__(128) void gemm_f16(const __half* __restrict__ A,
                                                const __half* __restrict__ B,
                                                float* __restrict__ C,
                                                int M, int N, int K, int ldc) {
    extern __shared__ char sm4[];

    const int tid = threadIdx.x;
    const int warp = tid >> 5;
    const int lane = tid & 31;
    const int r = lane >> 2;
    const int cc = lane & 3;
    const int bm0 = blockIdx.y * BM4;
    const int bn0 = blockIdx.x * BN4;
    const int nk = K / BK4;

    auto issue = [&](int kt) {
        char* As = sm4 + (kt & 1) * STG4_B;
        char* Bs = As + BM4 * ST4 * 4;
        const int k0 = kt * BK4;
#pragma unroll
        for (int i = 0; i < 8; i++) {      // A: 128 rows x 8 chunks(16B=8 halfs)
            int task = tid + i * 128;
            int row = task >> 3, ch = task & 7;
            cp_async16(As + row * 144 + ch * 16,
                       &A[(size_t)(bm0 + row) * K + k0 + ch * 8]);
        }
#pragma unroll
        for (int i = 0; i < 4; i++) {      // B: 64 rows x 8 chunks
            int task = tid + i * 128;
            int row = task >> 3, ch = task & 7;
            cp_async16(Bs + row * 144 + ch * 16,
                       &B[(size_t)(bn0 + row) * K + k0 + ch * 8]);
        }
        CP_COMMIT();
    };

    issue(0);
    if (nk > 1) issue(1);

    float acc[2][8][4];
#pragma unroll
    for (int mt = 0; mt < 2; mt++)
#pragma unroll
        for (int nt = 0; nt < 8; nt++)
#pragma unroll
            for (int i = 0; i < 4; i++) acc[mt][nt][i] = 0.0f;

    for (int kt = 0; kt < nk; kt++) {
        if (kt == nk - 1) asm volatile("cp.async.wait_group 0;" ::: "memory");
        else              asm volatile("cp.async.wait_group 1;" ::: "memory");
        __syncthreads();

        const unsigned* As2 = (const unsigned*)(sm4 + (kt & 1) * STG4_B);
        const unsigned* Bs2 = As2 + BM4 * ST4;

#pragma unroll
        for (int ks = 0; ks < 4; ks++) {    // 4 x k16
            unsigned af[2][4];
#pragma unroll
            for (int mt = 0; mt < 2; mt++) {
                int m0 = warp * 32 + mt * 16;
                af[mt][0] = As2[(m0 + r) * ST4 + ks * 8 + cc];
                af[mt][1] = As2[(m0 + r + 8) * ST4 + ks * 8 + cc];
                af[mt][2] = As2[(m0 + r) * ST4 + ks * 8 + cc + 4];
                af[mt][3] = As2[(m0 + r + 8) * ST4 + ks * 8 + cc + 4];
            }
            unsigned bf[8][2];
#pragma unroll
            for (int nt = 0; nt < 8; nt++) {
                int n0 = nt * 8 + r;
                bf[nt][0] = Bs2[n0 * ST4 + ks * 8 + cc];
                bf[nt][1] = Bs2[n0 * ST4 + ks * 8 + cc + 4];
            }
#pragma unroll
            for (int mt = 0; mt < 2; mt++)
#pragma unroll
                for (int nt = 0; nt < 8; nt++)
                    mma_f16(acc[mt][nt], af[mt], bf[nt]);
        }
        __syncthreads();
        if (kt + 2 < nk) issue(kt + 2);
    }

    // epilogue
#pragma unroll
    for (int mt = 0; mt < 2; mt++) {
#pragma unroll
        for (int nt = 0; nt < 8; nt++) {
            int row = bm0 + warp * 32 + mt * 16 + r;
            int col = bn0 + nt * 8 + 2 * cc;
            float2 v0 = make_float2(acc[mt][nt][0], acc[mt][nt][1]);
            float2 v1 = make_float2(acc[mt][nt][2], acc[mt][nt][3]);
            *(float2*)&C[(size_t)row * ldc + col] = v0;
            *(float2*)&C[(size_t)(row + 8) * ldc + col] = v1;
        }
    }
}

// ----------------------------------------------------------------------------
// RMSNorm + RoPE for Q (writes g_Qh fp16)
// ----------------------------------------------------------------------------
__global__ void norm_rope_q_kernel(const float* __restrict__ src, __half* __restrict__ dst,
                                   const float* __restrict__ w) {
    int s = blockIdx.x;
    int h = blockIdx.y;
    int d = threadIdx.x;

    __shared__ float sh[HEAD_DIM];
    __shared__ float red[4];

    float x = src[(size_t)s * QKVDIM + h * HEAD_DIM + d];

    float sq = x * x;
#pragma unroll
    for (int off = 16; off > 0; off >>= 1)
        sq += __shfl_down_sync(0xffffffff, sq, off);
    if ((d & 31) == 0) red[d >> 5] = sq;
    __syncthreads();
    float var = (red[0] + red[1] + red[2] + red[3]) * (1.0f / HEAD_DIM);
    float r = rsqrtf(var + EPS);
    float xn = x * r * w[d];
    sh[d] = xn;
    __syncthreads();

    int f = d & 63;
    float inv_freq = powf(ROPE_THETA, -((float)f) / 64.0f);
    float ang = (float)s * inv_freq;
    float c = cosf(ang), sn = sinf(ang);
    float out;
    if (d < 64) out = xn * c - sh[d + 64] * sn;
    else        out = xn * c + sh[d - 64] * sn;

    dst[(size_t)s * QDIM + h * HEAD_DIM + d] = __float2half_rn(out);
}

// ----------------------------------------------------------------------------
// RMSNorm + RoPE for K (-> cache_k fp32 + g_Krh fp16) AND V copy
// (-> cache_v fp32 + g_Vrh fp16).
// ----------------------------------------------------------------------------
__global__ void norm_rope_kv_kernel(const float* __restrict__ src,
                                    float* __restrict__ cacheK, __half* __restrict__ Kr,
                                    float* __restrict__ cacheV, __half* __restrict__ Vr,
                                    const float* __restrict__ w) {
    int s = blockIdx.x;
    int h = blockIdx.y;
    int d = threadIdx.x;

    __shared__ float sh[HEAD_DIM];
    __shared__ float red[4];

    float x = src[(size_t)s * QKVDIM + QDIM + h * HEAD_DIM + d];

    float sq = x * x;
#pragma unroll
    for (int off = 16; off > 0; off >>= 1)
        sq += __shfl_down_sync(0xffffffff, sq, off);
    if ((d & 31) == 0) red[d >> 5] = sq;
    __syncthreads();
    float var = (red[0] + red[1] + red[2] + red[3]) * (1.0f / HEAD_DIM);
    float r = rsqrtf(var + EPS);
    float xn = x * r * w[d];
    sh[d] = xn;
    __syncthreads();

    int f = d & 63;
    float inv_freq = powf(ROPE_THETA, -((float)f) / 64.0f);
    float ang = (float)s * inv_freq;
    float c = cosf(ang), sn = sinf(ang);
    float out;
    if (d < 64) out = xn * c - sh[d + 64] * sn;
    else        out = xn * c + sh[d - 64] * sn;

    size_t idx = ((size_t)h * S + s) * HEAD_DIM + d;
    cacheK[idx] = out;
    Kr[idx] = __float2half_rn(out);

    float v = src[(size_t)s * QKVDIM + QDIM + KVDIM + h * HEAD_DIM + d];
    cacheV[idx] = v;
    Vr[idx] = __float2half_rn(v);
}

// ----------------------------------------------------------------------------
// Flash attention, fp16 mma. Block 128 threads (4 warps, 2x2), 64-query tile.
// smem (bytes):
//   Qs  half 64x136   @ 0      (17408)
//   KV  half K:64x136 / V^T:128x72  @ 17408 (18432)
//   Ps  f32  64x68    @ 35840  (17408)
//   Ph  half 64x72    @ 53248  (9216)
//   mS/lS/corr f32[64] @ 62464/62720/62976
// total 63232 B
// ----------------------------------------------------------------------------
#define F_QS 0
#define F_KV 17408
#define F_PS 35840
#define F_PH 53248
#define F_MS 62464
#define F_LS 62720
#define F_CS 62976
#define F_TOT 63232
#define FQT 64
#define FKT 64

__global__ __launch_bounds__(128) void flash_f16(const __half* __restrict__ Kr,
                                                 const __half* __restrict__ Vr) {
    extern __shared__ char fsc[];
    __half* Qs = (__half*)(fsc + F_QS);        // stride 136 halfs
    __half* KVh = (__half*)(fsc + F_KV);       // K: 136 / V^T: 72
    float* Ps = (float*)(fsc + F_PS);          // stride 68
    __half* Ph = (__half*)(fsc + F_PH);        // stride 72
    float* mS = (float*)(fsc + F_MS);
    float* lS = (float*)(fsc + F_LS);
    float* corrS = (float*)(fsc + F_CS);

    const unsigned* Qs2 = (const unsigned*)Qs;   // stride 68 half2
    const unsigned* KV2 = (const unsigned*)KVh;  // K: 68 / V^T: 36
    const unsigned* Ph2 = (const unsigned*)Ph;   // stride 36

    const int qTile = blockIdx.x;
    const int h = blockIdx.y;
    const int g = h >> 2;
    const int tid = threadIdx.x;
    const int warp = tid >> 5;
    const int lane = tid & 31;
    const int wm = warp >> 1;
    const int wn = warp & 1;
    const int r = lane >> 2;
    const int cc = lane & 3;
    const int qBase = qTile * FQT;
    const float scale = 0.08838834764831845f;

    if (tid < 64) { mS[tid] = -INFINITY; lS[tid] = 0.0f; }

    // load Q tile (64 x 128 halfs): 1024 16B-chunks... 64 rows x 16 chunks of 8 halfs
#pragma unroll
    for (int i = 0; i < 8; i++) {
        int idx = tid + i * 128;
        int row = idx >> 4, ch = idx & 15;
        uint4 v = *(const uint4*)&g_Qh[(size_t)(qBase + row) * QDIM + h * HEAD_DIM + ch * 8];
        *(uint4*)((char*)Qs + row * 272 + ch * 16) = v;
    }

    float oacc[2][8][4];
#pragma unroll
    for (int mt = 0; mt < 2; mt++)
#pragma unroll
        for (int nt = 0; nt < 8; nt++)
#pragma unroll
            for (int i = 0; i < 4; i++) oacc[mt][nt][i] = 0.0f;

    __syncthreads();

    for (int kt = 0; kt <= qTile; kt++) {
        const int kBase = kt * FKT;

        // load K tile (64 x 128 halfs)
#pragma unroll
        for (int i = 0; i < 8; i++) {
            int idx = tid + i * 128;
            int row = idx >> 4, ch = idx & 15;
            uint4 v = *(const uint4*)&Kr[((size_t)g * S + kBase + row) * HEAD_DIM + ch * 8];
            *(uint4*)((char*)KVh + row * 272 + ch * 16) = v;
        }
        __syncthreads();

        // S = Q K^T (64x64, k=128 -> 8 k16 steps), warp tile 32x32
        float sacc[2][4][4];
#pragma unroll
        for (int mt = 0; mt < 2; mt++)
#pragma unroll
            for (int nt = 0; nt < 4; nt++)
#pragma unroll
                for (int i = 0; i < 4; i++) sacc[mt][nt][i] = 0.0f;

#pragma unroll
        for (int ks = 0; ks < 8; ks++) {
            unsigned af[2][4];
#pragma unroll
            for (int mt = 0; mt < 2; mt++) {
                int m0 = wm * 32 + mt * 16;
                af[mt][0] = Qs2[(m0 + r) * 68 + ks * 8 + cc];
                af[mt][1] = Qs2[(m0 + r + 8) * 68 + ks * 8 + cc];
                af[mt][2] = Qs2[(m0 + r) * 68 + ks * 8 + cc + 4];
                af[mt][3] = Qs2[(m0 + r + 8) * 68 + ks * 8 + cc + 4];
            }
            unsigned bf[4][2];
#pragma unroll
            for (int nt = 0; nt < 4; nt++) {
                int n0 = wn * 32 + nt * 8 + r;
                bf[nt][0] = KV2[n0 * 68 + ks * 8 + cc];
                bf[nt][1] = KV2[n0 * 68 + ks * 8 + cc + 4];
            }
#pragma unroll
            for (int mt = 0; mt < 2; mt++)
#pragma unroll
                for (int nt = 0; nt < 4; nt++)
                    mma_f16(sacc[mt][nt], af[mt], bf[nt]);
        }

        // write masked, scaled S to Ps (fp32)
#pragma unroll
        for (int mt = 0; mt < 2; mt++) {
#pragma unroll
            for (int nt = 0; nt < 4; nt++) {
                int row0 = wm * 32 + mt * 16 + r;
                int col0 = wn * 32 + nt * 8 + 2 * cc;
                int qi0 = qBase + row0, qi1 = qi0 + 8;
                int kj0 = kBase + col0, kj1 = kj0 + 1;
                Ps[row0 * 68 + col0]       = (kj0 <= qi0) ? sacc[mt][nt][0] * scale : -1e30f;
                Ps[row0 * 68 + col0 + 1]   = (kj1 <= qi0) ? sacc[mt][nt][1] * scale : -1e30f;
                Ps[(row0 + 8) * 68 + col0]     = (kj0 <= qi1) ? sacc[mt][nt][2] * scale : -1e30f;
                Ps[(row0 + 8) * 68 + col0 + 1] = (kj1 <= qi1) ? sacc[mt][nt][3] * scale : -1e30f;
            }
        }
        __syncthreads();

        // load V^T (128 dims x 64 s, halfs, row stride 72) — K dead now
#pragma unroll
        for (int i = 0; i < 8; i++) {
            int idx = tid + i * 128;
            int s = idx & 63, c4 = idx >> 6;   // c4: 0..15 (8-half chunk of dims)
            uint4 v = *(const uint4*)&Vr[((size_t)g * S + kBase + s) * HEAD_DIM + c4 * 8];
            const __half* hv = (const __half*)&v;
#pragma unroll
            for (int j = 0; j < 8; j++)
                KVh[(c4 * 8 + j) * 72 + s] = hv[j];
        }

        // online softmax (fp32), P stored fp16 into Ph
        {
            int row = tid >> 1;
            int half_i = tid & 1;
            float* prow = &Ps[row * 68 + half_i * 32];
            __half* phrow = &Ph[row * 72 + half_i * 32];
            float mloc = -INFINITY;
#pragma unroll 8
            for (int j = 0; j < 32; j++) mloc = fmaxf(mloc, prow[j]);
            mloc = fmaxf(mloc, __shfl_xor_sync(0xffffffffu, mloc, 1));
            float mprev = mS[row];
            float mnew = fmaxf(mprev, mloc);
            float lsum = 0.0f;
#pragma unroll 8
            for (int j = 0; j < 32; j++) {
                float p = __expf(prow[j] - mnew);
                lsum += p;
                phrow[j] = __float2half_rn(p);
            }
            lsum += __shfl_xor_sync(0xffffffffu, lsum, 1);
            if (half_i == 0) {
                float corr = __expf(mprev - mnew);
                corrS[row] = corr;
                lS[row] = lS[row] * corr + lsum;
                mS[row] = mnew;
            }
        }
        __syncthreads();

        // rescale O accumulators
#pragma unroll
        for (int mt = 0; mt < 2; mt++) {
            int row0 = wm * 32 + mt * 16 + r;
            float cr0 = corrS[row0];
            float cr1 = corrS[row0 + 8];
#pragma unroll
            for (int nt = 0; nt < 8; nt++) {
                oacc[mt][nt][0] *= cr0; oacc[mt][nt][1] *= cr0;
                oacc[mt][nt][2] *= cr1; oacc[mt][nt][3] *= cr1;
            }
        }

        // O += P @ V (k=64 -> 4 k16 steps), warp tile 32x64
#pragma unroll
        for (int ks = 0; ks < 4; ks++) {
            unsigned af[2][4];
#pragma unroll
            for (int mt = 0; mt < 2; mt++) {
                int m0 = wm * 32 + mt * 16;
                af[mt][0] = Ph2[(m0 + r) * 36 + ks * 8 + cc];
                af[mt][1] = Ph2[(m0 + r + 8) * 36 + ks * 8 + cc];
                af[mt][2] = Ph2[(m0 + r) * 36 + ks * 8 + cc + 4];
                af[mt][3] = Ph2[(m0 + r + 8) * 36 + ks * 8 + cc + 4];
            }
#pragma unroll
            for (int nt = 0; nt < 8; nt++) {
                int n0 = wn * 64 + nt * 8 + r;
                unsigned bf[2];
                bf[0] = KV2[n0 * 36 + ks * 8 + cc];
                bf[1] = KV2[n0 * 36 + ks * 8 + cc + 4];
#pragma unroll
                for (int mt = 0; mt < 2; mt++)
                    mma_f16(oacc[mt][nt], af[mt], bf);
            }
        }
        __syncthreads();
    }

    // epilogue: normalize, write fp16 O
#pragma unroll
    for (int mt = 0; mt < 2; mt++) {
        int row0 = wm * 32 + mt * 16 + r;
        float li0 = 1.0f / lS[row0];
        float li1 = 1.0f / lS[row0 + 8];
#pragma unroll
        for (int nt = 0; nt < 8; nt++) {
            int col = wn * 64 + nt * 8 + 2 * cc;
            __half2 v0 = __floats2half2_rn(oacc[mt][nt][0] * li0, oacc[mt][nt][1] * li0);
            __half2 v1 = __floats2half2_rn(oacc[mt][nt][2] * li1, oacc[mt][nt][3] * li1);
            *(unsigned*)&g_Oh[(size_t)(qBase + row0) * QDIM + h * HEAD_DIM + col] = *(unsigned*)&v0;
            *(unsigned*)&g_Oh[(size_t)(qBase + row0 + 8) * QDIM + h * HEAD_DIM + col] = *(unsigned*)&v1;
        }
    }
}

// ----------------------------------------------------------------------------
extern "C" void kernel_launch(void* const* d_in, const int* in_sizes, int n_in,
                              void* d_out, int out_size) {
    const float* x  = (const float*)d_in[0];
    const float* Wq = (const float*)d_in[1];
    const float* Wk = (const float*)d_in[2];
    const float* Wv = (const float*)d_in[3];
    const float* Wo = (const float*)d_in[4];
    const float* qw = (const float*)d_in[5];
    const float* kw = (const float*)d_in[6];

    float* out    = (float*)d_out;
    float* cacheK = out + (size_t)S * D_MODEL;
    float* cacheV = cacheK + (size_t)NUM_KV_HEADS * S * HEAD_DIM;

    __half* dXh;   cudaGetSymbolAddress((void**)&dXh, g_Xh);
    __half* dWqkvh;cudaGetSymbolAddress((void**)&dWqkvh, g_Wqkvh);
    __half* dWoh;  cudaGetSymbolAddress((void**)&dWoh, g_Woh);
    float*  dQKV;  cudaGetSymbolAddress((void**)&dQKV, g_QKV);
    __half* dQh;   cudaGetSymbolAddress((void**)&dQh, g_Qh);
    __half* dKrh;  cudaGetSymbolAddress((void**)&dKrh, g_Krh);
    __half* dVrh;  cudaGetSymbolAddress((void**)&dVrh, g_Vrh);
    __half* dOh;   cudaGetSymbolAddress((void**)&dOh, g_Oh);

    cudaFuncSetAttribute(gemm_f16, cudaFuncAttributeMaxDynamicSharedMemorySize, G4_SMEM);

    // (1) convert all inputs to fp16
    round_all_kernel<<<(R_TOT + 255) / 256, 256>>>(x, Wq, Wk, Wv, Wo);

    // (2) fused QKV projection: [2048, 6144] = X @ [Wq;Wk;Wv]^T
    gemm_f16<<<dim3(QKVDIM / BN4, S / BM4), 128, G4_SMEM>>>(
        dXh, dWqkvh, dQKV, S, QKVDIM, D_MODEL, QKVDIM);

    // (3) Q norm+rope -> g_Qh
    norm_rope_q_kernel<<<dim3(S, NUM_HEADS), HEAD_DIM>>>(dQKV, dQh, qw);

    // (4) K norm+rope -> cache_k fp32 + g_Krh, V -> cache_v fp32 + g_Vrh
    norm_rope_kv_kernel<<<dim3(S, NUM_KV_HEADS), HEAD_DIM>>>(
        dQKV, cacheK, dKrh, cacheV, dVrh, kw);

    // (5) Flash attention (profiled launch slot)
    cudaFuncSetAttribute(flash_f16, cudaFuncAttributeMaxDynamicSharedMemorySize, F_TOT);
    flash_f16<<<dim3(S / FQT, NUM_HEADS), 128, F_TOT>>>(dKrh, dVrh);

    // (6) Output projection: out = O @ Wo^T
    gemm_f16<<<dim3(D_MODEL / BN4, S / BM4), 128, G4_SMEM>>>(
        dOh, dWoh, out, S, D_MODEL, QDIM, D_MODEL);
}

// round 11
// speedup vs baseline: 2.4648x; 1.0082x over previous
#include <cuda_runtime.h>
#include <cuda_fp16.h>
#include <math.h>
#include <stdint.h>

// Problem constants
#define S 2048
#define D_MODEL 2560
#define NUM_HEADS 32
#define NUM_KV_HEADS 8
#define HEAD_DIM 128
#define QDIM (NUM_HEADS * HEAD_DIM)     // 4096
#define KVDIM (NUM_KV_HEADS * HEAD_DIM) // 1024
#define QKVDIM (QDIM + 2 * KVDIM)       // 6144
#define EPS 1e-6f
#define ROPE_THETA 5000000.0f

// Scratch (no allocs allowed -> __device__ globals)
__device__ __half g_Xh[S * D_MODEL];
__device__ __half g_Wqkvh[QKVDIM * D_MODEL];
__device__ __half g_Woh[D_MODEL * QDIM];
__device__ float  g_QKV[S * QKVDIM];
__device__ __half g_Qh[S * QDIM];
__device__ __half g_Krh[NUM_KV_HEADS * S * HEAD_DIM];
__device__ __half g_Vrh[NUM_KV_HEADS * S * HEAD_DIM];
__device__ __half g_Oh[S * QDIM];

// ----------------------------------------------------------------------------
// helpers
// ----------------------------------------------------------------------------
__device__ __forceinline__ void mma_f16(float* d, const unsigned* a, const unsigned* b) {
    asm volatile(
        "mma.sync.aligned.m16n8k16.row.col.f32.f16.f16.f32 "
        "{%0,%1,%2,%3}, {%4,%5,%6,%7}, {%8,%9}, {%0,%1,%2,%3};"
        : "+f"(d[0]), "+f"(d[1]), "+f"(d[2]), "+f"(d[3])
        : "r"(a[0]), "r"(a[1]), "r"(a[2]), "r"(a[3]), "r"(b[0]), "r"(b[1]));
}

__device__ __forceinline__ void ldsm_x4(unsigned* r, uint32_t addr) {
    asm volatile("ldmatrix.sync.aligned.m8n8.x4.shared.b16 {%0,%1,%2,%3}, [%4];"
                 : "=r"(r[0]), "=r"(r[1]), "=r"(r[2]), "=r"(r[3]) : "r"(addr));
}

__device__ __forceinline__ void cp_async16(void* smem_dst, const void* gmem_src) {
    unsigned saddr = (unsigned)__cvta_generic_to_shared(smem_dst);
    asm volatile("cp.async.cg.shared.global [%0], [%1], 16;" :: "r"(saddr), "l"(gmem_src));
}
#define CP_COMMIT() asm volatile("cp.async.commit_group;")

__device__ __forceinline__ uint32_t smem_u32(const void* p) {
    uint32_t a;
    asm("{ .reg .u64 t; cvta.to.shared.u64 t, %1; cvt.u32.u64 %0, t; }" : "=r"(a) : "l"(p));
    return a;
}

// ----------------------------------------------------------------------------
// Fused conversion of all inputs to fp16 (RNE). One launch.
// ----------------------------------------------------------------------------
#define R_N1 (S * D_MODEL / 4)
#define R_N2 (QDIM * D_MODEL / 4)
#define R_N3 (KVDIM * D_MODEL / 4)
#define R_TOT (R_N1 + R_N2 + 2 * R_N3 + R_N2)

__global__ void round_all_kernel(const float* __restrict__ x,
                                 const float* __restrict__ Wq,
                                 const float* __restrict__ Wk,
                                 const float* __restrict__ Wv,
                                 const float* __restrict__ Wo) {
    long i = (long)blockIdx.x * blockDim.x + threadIdx.x;
    if (i >= R_TOT) return;
    const float4* src;
    __half* dst;
    if (i < R_N1) {
        src = (const float4*)x;
        dst = g_Xh;
    } else if (i < R_N1 + R_N2) {
        i -= R_N1;
        src = (const float4*)Wq;
        dst = g_Wqkvh;
    } else if (i < R_N1 + R_N2 + R_N3) {
        i -= R_N1 + R_N2;
        src = (const float4*)Wk;
        dst = g_Wqkvh + (size_t)QDIM * D_MODEL;
    } else if (i < R_N1 + R_N2 + 2 * R_N3) {
        i -= R_N1 + R_N2 + R_N3;
        src = (const float4*)Wv;
        dst = g_Wqkvh + (size_t)(QDIM + KVDIM) * D_MODEL;
    } else {
        i -= R_N1 + R_N2 + 2 * R_N3;
        src = (const float4*)Wo;
        dst = g_Woh;
    }
    float4 v = src[i];
    __half2 h0 = __floats2half2_rn(v.x, v.y);
    __half2 h1 = __floats2half2_rn(v.z, v.w);
    uint2 pk = make_uint2(*(unsigned*)&h0, *(unsigned*)&h1);
    *(uint2*)&dst[i * 4] = pk;
}

// ----------------------------------------------------------------------------
// fp16 NT GEMM with ldmatrix fragment loads.
// Block 128x64, 128 threads (4 warps, warp tile 32x64), mma m16n8k16.
// BK=64 halfs; 2-stage cp.async; row stride 72 halfs (144B, ==16 mod 128:
// conflict-free for both cp.async stores and ldmatrix reads).
// ----------------------------------------------------------------------------
#define BM4 128
#define BN4 64
#define BK4 64
#define ROWB 144                          // bytes per smem row
#define STG4_B ((BM4 + BN4) * ROWB)       // 27648
#define G4_SMEM (2 * STG4_B)              // 55296

__global__ __launch_bounds__(128) void gemm_f16(const __half* __restrict__ A,
                                                const __half* __restrict__ B,
                                                float* __restrict__ C,
                                                int M, int N, int K, int ldc) {
    extern __shared__ char sm4[];
    const uint32_t sbase = smem_u32(sm4);

    const int tid = threadIdx.x;
    const int warp = tid >> 5;
    const int lane = tid & 31;
    const int r = lane >> 2;
    const int cc = lane & 3;
    const int bm0 = blockIdx.y * BM4;
    const int bn0 = blockIdx.x * BN4;
    const int nk = K / BK4;

    // ldmatrix per-lane addressing: row = (lane&15), k-half = (lane>>4)*8
    const uint32_t lmrow = (lane & 15);
    const uint32_t lmk = (lane >> 4) * 16;   // bytes

    auto issue = [&](int kt) {
        char* As = sm4 + (kt & 1) * STG4_B;
        char* Bs = As + BM4 * ROWB;
        const int k0 = kt * BK4;
#pragma unroll
        for (int i = 0; i < 8; i++) {
            int task = tid + i * 128;
            int row = task >> 3, ch = task & 7;
            cp_async16(As + row * ROWB + ch * 16,
                       &A[(size_t)(bm0 + row) * K + k0 + ch * 8]);
        }
#pragma unroll
        for (int i = 0; i < 4; i++) {
            int task = tid + i * 128;
            int row = task >> 3, ch = task & 7;
            cp_async16(Bs + row * ROWB + ch * 16,
                       &B[(size_t)(bn0 + row) * K + k0 + ch * 8]);
        }
        CP_COMMIT();
    };

    issue(0);
    if (nk > 1) issue(1);

    float acc[2][8][4];
#pragma unroll
    for (int mt = 0; mt < 2; mt++)
#pragma unroll
        for (int nt = 0; nt < 8; nt++)
#pragma unroll
            for (int i = 0; i < 4; i++) acc[mt][nt][i] = 0.0f;

    for (int kt = 0; kt < nk; kt++) {
        if (kt == nk - 1) asm volatile("cp.async.wait_group 0;" ::: "memory");
        else              asm volatile("cp.async.wait_group 1;" ::: "memory");
        __syncthreads();

        const uint32_t stA = sbase + (kt & 1) * STG4_B;
        const uint32_t stB = stA + BM4 * ROWB;
        // A: rows warp*32 + mt*16 + lmrow;  B: rows p*16 + lmrow
        const uint32_t aAddr0 = stA + (warp * 32 + lmrow) * ROWB + lmk;
        const uint32_t bAddr0 = stB + lmrow * ROWB + lmk;

#pragma unroll
        for (int ks = 0; ks < 4; ks++) {
            const uint32_t ko = ks * 32;    // bytes per k16 step
            unsigned af[2][4];
            ldsm_x4(af[0], aAddr0 + ko);
            ldsm_x4(af[1], aAddr0 + 16 * ROWB + ko);
            unsigned bf[4][4];   // pair p: {b0(nt=2p), b0(2p+1), b1(2p), b1(2p+1)}
#pragma unroll
            for (int p = 0; p < 4; p++)
                ldsm_x4(bf[p], bAddr0 + p * 16 * ROWB + ko);
#pragma unroll
            for (int mt = 0; mt < 2; mt++)
#pragma unroll
                for (int nt = 0; nt < 8; nt++) {
                    unsigned b[2] = { bf[nt >> 1][nt & 1], bf[nt >> 1][2 + (nt & 1)] };
                    mma_f16(acc[mt][nt], af[mt], b);
                }
        }
        __syncthreads();
        if (kt + 2 < nk) issue(kt + 2);
    }

    // epilogue
#pragma unroll
    for (int mt = 0; mt < 2; mt++) {
#pragma unroll
        for (int nt = 0; nt < 8; nt++) {
            int row = bm0 + warp * 32 + mt * 16 + r;
            int col = bn0 + nt * 8 + 2 * cc;
            float2 v0 = make_float2(acc[mt][nt][0], acc[mt][nt][1]);
            float2 v1 = make_float2(acc[mt][nt][2], acc[mt][nt][3]);
            *(float2*)&C[(size_t)row * ldc + col] = v0;
            *(float2*)&C[(size_t)(row + 8) * ldc + col] = v1;
        }
    }
}

// ----------------------------------------------------------------------------
// RMSNorm + RoPE for Q (writes g_Qh fp16)
// ----------------------------------------------------------------------------
__global__ void norm_rope_q_kernel(const float* __restrict__ src, __half* __restrict__ dst,
                                   const float* __restrict__ w) {
    int s = blockIdx.x;
    int h = blockIdx.y;
    int d = threadIdx.x;

    __shared__ float sh[HEAD_DIM];
    __shared__ float red[4];

    float x = src[(size_t)s * QKVDIM + h * HEAD_DIM + d];

    float sq = x * x;
#pragma unroll
    for (int off = 16; off > 0; off >>= 1)
        sq += __shfl_down_sync(0xffffffff, sq, off);
    if ((d & 31) == 0) red[d >> 5] = sq;
    __syncthreads();
    float var = (red[0] + red[1] + red[2] + red[3]) * (1.0f / HEAD_DIM);
    float r = rsqrtf(var + EPS);
    float xn = x * r * w[d];
    sh[d] = xn;
    __syncthreads();

    int f = d & 63;
    float inv_freq = powf(ROPE_THETA, -((float)f) / 64.0f);
    float ang = (float)s * inv_freq;
    float c = cosf(ang), sn = sinf(ang);
    float out;
    if (d < 64) out = xn * c - sh[d + 64] * sn;
    else        out = xn * c + sh[d - 64] * sn;

    dst[(size_t)s * QDIM + h * HEAD_DIM + d] = __float2half_rn(out);
}

// ----------------------------------------------------------------------------
// RMSNorm + RoPE for K (-> cache_k fp32 + g_Krh fp16) AND V copy
// ----------------------------------------------------------------------------
__global__ void norm_rope_kv_kernel(const float* __restrict__ src,
                                    float* __restrict__ cacheK, __half* __restrict__ Kr,
                                    float* __restrict__ cacheV, __half* __restrict__ Vr,
                                    const float* __restrict__ w) {
    int s = blockIdx.x;
    int h = blockIdx.y;
    int d = threadIdx.x;

    __shared__ float sh[HEAD_DIM];
    __shared__ float red[4];

    float x = src[(size_t)s * QKVDIM + QDIM + h * HEAD_DIM + d];

    float sq = x * x;
#pragma unroll
    for (int off = 16; off > 0; off >>= 1)
        sq += __shfl_down_sync(0xffffffff, sq, off);
    if ((d & 31) == 0) red[d >> 5] = sq;
    __syncthreads();
    float var = (red[0] + red[1] + red[2] + red[3]) * (1.0f / HEAD_DIM);
    float r = rsqrtf(var + EPS);
    float xn = x * r * w[d];
    sh[d] = xn;
    __syncthreads();

    int f = d & 63;
    float inv_freq = powf(ROPE_THETA, -((float)f) / 64.0f);
    float ang = (float)s * inv_freq;
    float c = cosf(ang), sn = sinf(ang);
    float out;
    if (d < 64) out = xn * c - sh[d + 64] * sn;
    else        out = xn * c + sh[d - 64] * sn;

    size_t idx = ((size_t)h * S + s) * HEAD_DIM + d;
    cacheK[idx] = out;
    Kr[idx] = __float2half_rn(out);

    float v = src[(size_t)s * QKVDIM + QDIM + KVDIM + h * HEAD_DIM + d];
    cacheV[idx] = v;
    Vr[idx] = __float2half_rn(v);
}

// ----------------------------------------------------------------------------
// Flash attention, fp16 mma + ldmatrix fragment loads.
// smem (bytes):
//   Qs  half 64x136   @ 0      (17408)   row stride 272B (==16 mod 128)
//   KV  half K:64x136 / V^T:128x72 @ 17408 (18432)   V^T row stride 144B
//   Ps  f32  64x68    @ 35840  (17408)
//   Ph  half 64x72    @ 53248  (9216)    row stride 144B
//   mS/lS/corr f32[64] @ 62464/62720/62976
// total 63232 B
// ----------------------------------------------------------------------------
#define F_QS 0
#define F_KV 17408
#define F_PS 35840
#define F_PH 53248
#define F_MS 62464
#define F_LS 62720
#define F_CS 62976
#define F_TOT 63232
#define FQT 64
#define FKT 64

__global__ __launch_bounds__(128) void flash_f16(const __half* __restrict__ Kr,
                                                 const __half* __restrict__ Vr) {
    extern __shared__ char fsc[];
    const uint32_t fsb = smem_u32(fsc);
    __half* Qs = (__half*)(fsc + F_QS);
    __half* KVh = (__half*)(fsc + F_KV);
    float* Ps = (float*)(fsc + F_PS);
    __half* Ph = (__half*)(fsc + F_PH);
    float* mS = (float*)(fsc + F_MS);
    float* lS = (float*)(fsc + F_LS);
    float* corrS = (float*)(fsc + F_CS);

    const int qTile = blockIdx.x;
    const int h = blockIdx.y;
    const int g = h >> 2;
    const int tid = threadIdx.x;
    const int warp = tid >> 5;
    const int lane = tid & 31;
    const int wm = warp >> 1;
    const int wn = warp & 1;
    const int r = lane >> 2;
    const int cc = lane & 3;
    const int qBase = qTile * FQT;
    const float scale = 0.08838834764831845f;

    const uint32_t lmrow = (lane & 15);
    const uint32_t lmk = (lane >> 4) * 16;

    if (tid < 64) { mS[tid] = -INFINITY; lS[tid] = 0.0f; }

    // load Q tile (64 x 128 halfs), row stride 272B
#pragma unroll
    for (int i = 0; i < 8; i++) {
        int idx = tid + i * 128;
        int row = idx >> 4, ch = idx & 15;
        uint4 v = *(const uint4*)&g_Qh[(size_t)(qBase + row) * QDIM + h * HEAD_DIM + ch * 8];
        *(uint4*)((char*)Qs + row * 272 + ch * 16) = v;
    }

    float oacc[2][8][4];
#pragma unroll
    for (int mt = 0; mt < 2; mt++)
#pragma unroll
        for (int nt = 0; nt < 8; nt++)
#pragma unroll
            for (int i = 0; i < 4; i++) oacc[mt][nt][i] = 0.0f;

    __syncthreads();

    // ldmatrix base addresses
    const uint32_t aQ0 = fsb + F_QS + (wm * 32 + lmrow) * 272 + lmk;
    const uint32_t bK0 = fsb + F_KV + (wn * 32 + lmrow) * 272 + lmk;
    const uint32_t aP0 = fsb + F_PH + (wm * 32 + lmrow) * 144 + lmk;
    const uint32_t bV0 = fsb + F_KV + (wn * 64 + lmrow) * 144 + lmk;

    for (int kt = 0; kt <= qTile; kt++) {
        const int kBase = kt * FKT;

        // load K tile (64 x 128 halfs), stride 272B
#pragma unroll
        for (int i = 0; i < 8; i++) {
            int idx = tid + i * 128;
            int row = idx >> 4, ch = idx & 15;
            uint4 v = *(const uint4*)&Kr[((size_t)g * S + kBase + row) * HEAD_DIM + ch * 8];
            *(uint4*)((char*)KVh + row * 272 + ch * 16) = v;
        }
        __syncthreads();

        // S = Q K^T (64x64, k=128 -> 8 k16 steps), warp tile 32x32
        float sacc[2][4][4];
#pragma unroll
        for (int mt = 0; mt < 2; mt++)
#pragma unroll
            for (int nt = 0; nt < 4; nt++)
#pragma unroll
                for (int i = 0; i < 4; i++) sacc[mt][nt][i] = 0.0f;

#pragma unroll
        for (int ks = 0; ks < 8; ks++) {
            const uint32_t ko = ks * 32;
            unsigned af[2][4];
            ldsm_x4(af[0], aQ0 + ko);
            ldsm_x4(af[1], aQ0 + 16 * 272 + ko);
            unsigned bf[2][4];  // pair p covers nt=2p,2p+1
            ldsm_x4(bf[0], bK0 + ko);
            ldsm_x4(bf[1], bK0 + 16 * 272 + ko);
#pragma unroll
            for (int mt = 0; mt < 2; mt++)
#pragma unroll
                for (int nt = 0; nt < 4; nt++) {
                    unsigned b[2] = { bf[nt >> 1][nt & 1], bf[nt >> 1][2 + (nt & 1)] };
                    mma_f16(sacc[mt][nt], af[mt], b);
                }
        }

        // write masked, scaled S to Ps (fp32)
#pragma unroll
        for (int mt = 0; mt < 2; mt++) {
#pragma unroll
            for (int nt = 0; nt < 4; nt++) {
                int row0 = wm * 32 + mt * 16 + r;
                int col0 = wn * 32 + nt * 8 + 2 * cc;
                int qi0 = qBase + row0, qi1 = qi0 + 8;
                int kj0 = kBase + col0, kj1 = kj0 + 1;
                Ps[row0 * 68 + col0]       = (kj0 <= qi0) ? sacc[mt][nt][0] * scale : -1e30f;
                Ps[row0 * 68 + col0 + 1]   = (kj1 <= qi0) ? sacc[mt][nt][1] * scale : -1e30f;
                Ps[(row0 + 8) * 68 + col0]     = (kj0 <= qi1) ? sacc[mt][nt][2] * scale : -1e30f;
                Ps[(row0 + 8) * 68 + col0 + 1] = (kj1 <= qi1) ? sacc[mt][nt][3] * scale : -1e30f;
            }
        }
        __syncthreads();

        // load V^T (128 dims x 64 s, row stride 144B) — K dead now
#pragma unroll
        for (int i = 0; i < 8; i++) {
            int idx = tid + i * 128;
            int s = idx & 63, c4 = idx >> 6;
            uint4 v = *(const uint4*)&Vr[((size_t)g * S + kBase + s) * HEAD_DIM + c4 * 8];
            const __half* hv = (const __half*)&v;
#pragma unroll
            for (int j = 0; j < 8; j++)
                KVh[(c4 * 8 + j) * 72 + s] = hv[j];
        }

        // online softmax (fp32), P stored fp16 into Ph
        {
            int row = tid >> 1;
            int half_i = tid & 1;
            float* prow = &Ps[row * 68 + half_i * 32];
            __half* phrow = &Ph[row * 72 + half_i * 32];
            float mloc = -INFINITY;
#pragma unroll 8
            for (int j = 0; j < 32; j++) mloc = fmaxf(mloc, prow[j]);
            mloc = fmaxf(mloc, __shfl_xor_sync(0xffffffffu, mloc, 1));
            float mprev = mS[row];
            float mnew = fmaxf(mprev, mloc);
            float lsum = 0.0f;
#pragma unroll 8
            for (int j = 0; j < 32; j++) {
                float p = __expf(prow[j] - mnew);
                lsum += p;
                phrow[j] = __float2half_rn(p);
            }
            lsum += __shfl_xor_sync(0xffffffffu, lsum, 1);
            if (half_i == 0) {
                float corr = __expf(mprev - mnew);
                corrS[row] = corr;
                lS[row] = lS[row] * corr + lsum;
                mS[row] = mnew;
            }
        }
        __syncthreads();

        // rescale O accumulators
#pragma unroll
        for (int mt = 0; mt < 2; mt++) {
            int row0 = wm * 32 + mt * 16 + r;
            float cr0 = corrS[row0];
            float cr1 = corrS[row0 + 8];
#pragma unroll
            for (int nt = 0; nt < 8; nt++) {
                oacc[mt][nt][0] *= cr0; oacc[mt][nt][1] *= cr0;
                oacc[mt][nt][2] *= cr1; oacc[mt][nt][3] *= cr1;
            }
        }

        // O += P @ V (k=64 -> 4 k16 steps), warp tile 32x64
#pragma unroll
        for (int ks = 0; ks < 4; ks++) {
            const uint32_t ko = ks * 32;
            unsigned af[2][4];
            ldsm_x4(af[0], aP0 + ko);
            ldsm_x4(af[1], aP0 + 16 * 144 + ko);
            unsigned bf[4][4];
#pragma unroll
            for (int p = 0; p < 4; p++)
                ldsm_x4(bf[p], bV0 + p * 16 * 144 + ko);
#pragma unroll
            for (int mt = 0; mt < 2; mt++)
#pragma unroll
                for (int nt = 0; nt < 8; nt++) {
                    unsigned b[2] = { bf[nt >> 1][nt & 1], bf[nt >> 1][2 + (nt & 1)] };
                    mma_f16(oacc[mt][nt], af[mt], b);
                }
        }
        __syncthreads();
    }

    // epilogue: normalize, write fp16 O
#pragma unroll
    for (int mt = 0; mt < 2; mt++) {
        int row0 = wm * 32 + mt * 16 + r;
        float li0 = 1.0f / lS[row0];
        float li1 = 1.0f / lS[row0 + 8];
#pragma unroll
        for (int nt = 0; nt < 8; nt++) {
            int col = wn * 64 + nt * 8 + 2 * cc;
            __half2 v0 = __floats2half2_rn(oacc[mt][nt][0] * li0, oacc[mt][nt][1] * li0);
            __half2 v1 = __floats2half2_rn(oacc[mt][nt][2] * li1, oacc[mt][nt][3] * li1);
            *(unsigned*)&g_Oh[(size_t)(qBase + row0) * QDIM + h * HEAD_DIM + col] = *(unsigned*)&v0;
            *(unsigned*)&g_Oh[(size_t)(qBase + row0 + 8) * QDIM + h * HEAD_DIM + col] = *(unsigned*)&v1;
        }
    }
}

// ----------------------------------------------------------------------------
extern "C" void kernel_launch(void* const* d_in, const int* in_sizes, int n_in,
                              void* d_out, int out_size) {
    const float* x  = (const float*)d_in[0];
    const float* Wq = (const float*)d_in[1];
    const float* Wk = (const float*)d_in[2];
    const float* Wv = (const float*)d_in[3];
    const float* Wo = (const float*)d_in[4];
    const float* qw = (const float*)d_in[5];
    const float* kw = (const float*)d_in[6];

    float* out    = (float*)d_out;
    float* cacheK = out + (size_t)S * D_MODEL;
    float* cacheV = cacheK + (size_t)NUM_KV_HEADS * S * HEAD_DIM;

    __half* dXh;   cudaGetSymbolAddress((void**)&dXh, g_Xh);
    __half* dWqkvh;cudaGetSymbolAddress((void**)&dWqkvh, g_Wqkvh);
    __half* dWoh;  cudaGetSymbolAddress((void**)&dWoh, g_Woh);
    float*  dQKV;  cudaGetSymbolAddress((void**)&dQKV, g_QKV);
    __half* dQh;   cudaGetSymbolAddress((void**)&dQh, g_Qh);
    __half* dKrh;  cudaGetSymbolAddress((void**)&dKrh, g_Krh);
    __half* dVrh;  cudaGetSymbolAddress((void**)&dVrh, g_Vrh);
    __half* dOh;   cudaGetSymbolAddress((void**)&dOh, g_Oh);

    cudaFuncSetAttribute(gemm_f16, cudaFuncAttributeMaxDynamicSharedMemorySize, G4_SMEM);

    // (1) convert all inputs to fp16
    round_all_kernel<<<(R_TOT + 255) / 256, 256>>>(x, Wq, Wk, Wv, Wo);

    // (2) fused QKV projection: [2048, 6144] = X @ [Wq;Wk;Wv]^T
    gemm_f16<<<dim3(QKVDIM / BN4, S / BM4), 128, G4_SMEM>>>(
        dXh, dWqkvh, dQKV, S, QKVDIM, D_MODEL, QKVDIM);

    // (3) Q norm+rope -> g_Qh
    norm_rope_q_kernel<<<dim3(S, NUM_HEADS), HEAD_DIM>>>(dQKV, dQh, qw);

    // (4) K norm+rope -> cache_k fp32 + g_Krh, V -> cache_v fp32 + g_Vrh
    norm_rope_kv_kernel<<<dim3(S, NUM_KV_HEADS), HEAD_DIM>>>(
        dQKV, cacheK, dKrh, cacheV, dVrh, kw);

    // (5) Flash attention (profiled launch slot)
    cudaFuncSetAttribute(flash_f16, cudaFuncAttributeMaxDynamicSharedMemorySize, F_TOT);
    flash_f16<<<dim3(S / FQT, NUM_HEADS), 128, F_TOT>>>(dKrh, dVrh);

    // (6) Output projection: out = O @ Wo^T
    gemm_f16<<<dim3(D_MODEL / BN4, S / BM4), 128, G4_SMEM>>>(
        dOh, dWoh, out, S, D_MODEL, QDIM, D_MODEL);
}